// round 10
// baseline (speedup 1.0000x reference)
#include <cuda_runtime.h>
#include <cuda_bf16.h>
#include <cstdint>

// ---------------- constants ----------------
#define NB    2
#define CIN   64
#define CD    32
#define HHd   24
#define WWd   24
#define NP    4608          // 8*24*24
#define TF    16
#define HF    48
#define WF    48
#define NTOT  (32*NP)
#define KT    128
#define NKT   (NP/KT)       // 36
#define QSCALE 0.72134752044482f   // 0.5 * log2(e): scores land in log2 domain

typedef unsigned long long u64;

// ---------------- scratch ----------------
__device__ float g_xr [NB*CIN*NP];
__device__ float g_xcr[NB*CIN*NP];
__device__ float g_xd [NB*CD*NP];
__device__ float g_xcd[NB*CD*NP];
// Q/K: per row 8 u64 slots; slot s = {lo32: bf16x2 hi-pair(ch 2s,2s+1), hi32: bf16x2 lo-pair}
__device__ __align__(16) u64 g_qhl[2*NB*NP*8];
__device__ __align__(16) u64 g_khl[2*NB*NP*8];
// V: per (ab,ch): NP/16 groups x 32B; group block: slot t(8B) = {pair(16g+2t,+1), pair(16g+2t+8,+9)}
__device__ __align__(16) char g_vp[(size_t)2*NB*32*NP*2];
__device__ float g_pacc[2*NB*2*32*NP];   // split-K unnormalized O partials
__device__ float g_pl  [2*NB*2*NP];      // split-K l partials
__device__ float g_ao [2][NB*32*NP];
__device__ float g_up [2][NB*64*NP];
__device__ double g_psum[4][8][2];

// ---------------- helpers ----------------
__device__ __forceinline__ uint32_t smem_u32(const void* p) {
    uint32_t a;
    asm("{ .reg .u64 t; cvta.to.shared.u64 t, %1; cvt.u32.u64 %0, t; }" : "=r"(a) : "l"(p));
    return a;
}
__device__ __forceinline__ uint32_t pkb(__nv_bfloat16 lo, __nv_bfloat16 hi) {
    return ((uint32_t)__bfloat16_as_ushort(hi) << 16) | (uint32_t)__bfloat16_as_ushort(lo);
}
__device__ __forceinline__ uint32_t pkbf2(float lo, float hi) {
    uint32_t r;
    asm("cvt.rn.bf16x2.f32 %0, %1, %2;" : "=r"(r) : "f"(hi), "f"(lo));
    return r;
}
__device__ __forceinline__ float ex2f(float x) {
    float r;
    asm("ex2.approx.f32 %0, %1;" : "=f"(r) : "f"(x));
    return r;
}
__device__ __forceinline__ void mma_bf16(float* c, const uint32_t* a, uint32_t b0, uint32_t b1) {
    asm volatile(
        "mma.sync.aligned.m16n8k16.row.col.f32.bf16.bf16.f32 "
        "{%0,%1,%2,%3}, {%4,%5,%6,%7}, {%8,%9}, {%0,%1,%2,%3};"
        : "+f"(c[0]), "+f"(c[1]), "+f"(c[2]), "+f"(c[3])
        : "r"(a[0]), "r"(a[1]), "r"(a[2]), "r"(a[3]), "r"(b0), "r"(b1));
}
__device__ __forceinline__ void cpa16(uint32_t dst, const void* src) {
    asm volatile("cp.async.cg.shared.global [%0], [%1], 16;" :: "r"(dst), "l"(src) : "memory");
}
#define CP_COMMIT() asm volatile("cp.async.commit_group;" ::: "memory")
#define CP_WAIT1()  asm volatile("cp.async.wait_group 1;" ::: "memory")
#define CP_WAIT0()  asm volatile("cp.async.wait_group 0;" ::: "memory")

// ---------------- K1: trilinear downsample ----------------
__global__ void k_resize(const float* __restrict__ x, const float* __restrict__ xc) {
    int i = blockIdx.x * 256 + threadIdx.x;
    const float* src = blockIdx.z ? xc : x;
    float* dst = blockIdx.z ? g_xcr : g_xr;
    int p  = i % NP;
    int bc = i / NP;
    int w = p % WWd, h = (p / WWd) % HHd, t = p / (WWd * HHd);

    float pt = (float)t * (15.0f / 7.0f);
    int t0 = (int)pt; float wt = pt - (float)t0; int t1 = min(t0 + 1, 15); t0 = min(t0, 15);
    float ph = (float)h * (47.0f / 23.0f);
    int h0 = (int)ph; float wh = ph - (float)h0; int h1 = min(h0 + 1, 47); h0 = min(h0, 47);
    float pw = (float)w * (47.0f / 23.0f);
    int w0 = (int)pw; float ww = pw - (float)w0; int w1 = min(w0 + 1, 47); w0 = min(w0, 47);

    const float* base = src + (size_t)bc * (TF * HF * WF);
#define ATI(ti,hi,wi) __ldg(base + (ti)*(HF*WF) + (hi)*WF + (wi))
    float c00 = ATI(t0,h0,w0); c00 += (ATI(t0,h0,w1) - c00) * ww;
    float c01 = ATI(t0,h1,w0); c01 += (ATI(t0,h1,w1) - c01) * ww;
    float c10 = ATI(t1,h0,w0); c10 += (ATI(t1,h0,w1) - c10) * ww;
    float c11 = ATI(t1,h1,w0); c11 += (ATI(t1,h1,w1) - c11) * ww;
#undef ATI
    float c0 = c00 + (c01 - c00) * wh;
    float c1 = c10 + (c11 - c10) * wh;
    dst[i] = c0 + (c1 - c0) * wt;
}

// ---------------- K2: down conv 64 -> 32 ----------------
__global__ __launch_bounds__(128) void k_down(
    const float* __restrict__ wd, const float* __restrict__ bd,
    const float* __restrict__ wdc, const float* __restrict__ bdc) {
    __shared__ float sw[CD * CIN];
    __shared__ float sb[CD];
    const float* w  = blockIdx.z ? wdc : wd;
    const float* bb = blockIdx.z ? bdc : bd;
    const float* in = blockIdx.z ? g_xcr : g_xr;
    float* out      = blockIdx.z ? g_xcd : g_xd;
    for (int i = threadIdx.x; i < CD * CIN; i += 128) sw[i] = w[i];
    if (threadIdx.x < CD) sb[threadIdx.x] = bb[threadIdx.x];
    __syncthreads();
    int idx = blockIdx.x * 128 + threadIdx.x;
    int b = idx / NP, p = idx % NP;
    float xin[CIN];
#pragma unroll
    for (int c = 0; c < CIN; c++) xin[c] = in[(b * CIN + c) * NP + p];
#pragma unroll
    for (int o = 0; o < CD; o++) {
        float acc = sb[o];
#pragma unroll
        for (int c = 0; c < CIN; c++) acc = fmaf(sw[o * CIN + c], xin[c], acc);
        out[(b * CD + o) * NP + p] = acc;
    }
}

// ---------------- K3: QKV projections + RoPE -> packed layouts ----------------
__device__ __forceinline__ void store_hl16i(u64* d, const float* v) {
#pragma unroll
    for (int i = 0; i < 8; i++) {
        float v0 = v[2 * i], v1 = v[2 * i + 1];
        __nv_bfloat16 h0 = __float2bfloat16(v0);
        __nv_bfloat16 h1 = __float2bfloat16(v1);
        __nv_bfloat16 e0 = __float2bfloat16(v0 - __bfloat162float(h0));
        __nv_bfloat16 e1 = __float2bfloat16(v1 - __bfloat162float(h1));
        d[i] = ((u64)pkb(e0, e1) << 32) | (u64)pkb(h0, h1);
    }
}
__device__ __forceinline__ void store_v(char* base_ab_ch, int p, float val) {
    int gi = p >> 4, r = p & 15;
    int ofs = ((r & 7) >> 1) * 8 + ((r >> 3) & 1) * 4 + (r & 1) * 2;
    *(__nv_bfloat16*)(base_ab_ch + (size_t)gi * 32 + ofs) = __float2bfloat16(val);
}

// z = 0: q,k,v (attn 0) ; z = 1: q_sa,k_sa,v_sa (attn 1)
__global__ __launch_bounds__(128) void k_proj(
    const float* __restrict__ wq,  const float* __restrict__ bq,
    const float* __restrict__ wk,  const float* __restrict__ bk,
    const float* __restrict__ wv,  const float* __restrict__ bv,
    const float* __restrict__ wqs, const float* __restrict__ bqs,
    const float* __restrict__ wks, const float* __restrict__ bks,
    const float* __restrict__ wvs, const float* __restrict__ bvs,
    const float* __restrict__ off, const float* __restrict__ offc) {
    int z = blockIdx.z;
    __shared__ float s_wq[512], s_wk[512], s_wv[1024];
    __shared__ float s_bq[16], s_bk[16], s_bv[32];
    {
        const float* WQ = z ? wqs : wq;
        const float* WK = z ? wks : wk;
        const float* WV = z ? wvs : wv;
        const float* BQ = z ? bqs : bq;
        const float* BK = z ? bks : bk;
        const float* BV = z ? bvs : bv;
        for (int i = threadIdx.x; i < 512; i += 128) { s_wq[i] = WQ[i]; s_wk[i] = WK[i]; }
        for (int i = threadIdx.x; i < 1024; i += 128) s_wv[i] = WV[i];
        if (threadIdx.x < 16) { s_bq[threadIdx.x] = BQ[threadIdx.x]; s_bk[threadIdx.x] = BK[threadIdx.x]; }
        if (threadIdx.x < 32) s_bv[threadIdx.x] = BV[threadIdx.x];
    }
    __syncthreads();

    int idx = blockIdx.x * 128 + threadIdx.x;
    int b = idx / NP, p = idx % NP, t = p / (HHd * WWd);
    int ab = z * NB + b;

    float xq[32], xcd[32];
#pragma unroll
    for (int c = 0; c < 32; c++) xcd[c] = g_xcd[(b * 32 + c) * NP + p];
    if (z == 0) {
#pragma unroll
        for (int c = 0; c < 32; c++) xq[c] = g_xd[(b * 32 + c) * NP + p];
    } else {
#pragma unroll
        for (int c = 0; c < 32; c++) xq[c] = xcd[c];
    }

    const float invf[8] = {1.0f, 0.31622776601683794f, 0.1f, 0.031622776601683794f,
                           0.01f, 0.0031622776601683794f, 0.001f, 0.00031622776601683794f};
    float se[8], ce[8], sk_[8], ck_[8];
    float tf = (float)t;
#pragma unroll
    for (int i = 0; i < 8; i++) {
        float a = tf * invf[i];
        float s = sinf(a), c = cosf(a);
        float o1 = off[i * 500 + t];             // q rope offset (both attns use `offset`)
        se[i] = s + o1; ce[i] = c + o1;          // same offset on sin AND cos (per reference)
        if (z == 0) {
            float o2 = offc[i * 500 + t];        // cross-attn k uses offset_c
            sk_[i] = s + o2; ck_[i] = c + o2;
        } else {
            sk_[i] = se[i]; ck_[i] = ce[i];      // self-attn k uses offset
        }
    }

    float tmp[16], rv[16];
    int row = ab * NP + p;

    // q = rope(Wq*xq + bq) * (0.5*log2e)  -> scores in log2 domain for ex2.approx
#pragma unroll
    for (int o = 0; o < 16; o++) {
        float acc = s_bq[o];
#pragma unroll
        for (int c = 0; c < 32; c++) acc = fmaf(s_wq[o * 32 + c], xq[c], acc);
        tmp[o] = acc;
    }
#pragma unroll
    for (int i = 0; i < 8; i++) {
        rv[i]     = QSCALE * (tmp[i] * ce[i] - tmp[8 + i] * se[i]);
        rv[8 + i] = QSCALE * (tmp[8 + i] * ce[i] + tmp[i] * se[i]);
    }
    store_hl16i(g_qhl + (size_t)row * 8, rv);

    // k = rope(Wk*xcd + bk)
#pragma unroll
    for (int o = 0; o < 16; o++) {
        float acc = s_bk[o];
#pragma unroll
        for (int c = 0; c < 32; c++) acc = fmaf(s_wk[o * 32 + c], xcd[c], acc);
        tmp[o] = acc;
    }
#pragma unroll
    for (int i = 0; i < 8; i++) {
        rv[i]     = tmp[i] * ck_[i] - tmp[8 + i] * sk_[i];
        rv[8 + i] = tmp[8 + i] * ck_[i] + tmp[i] * sk_[i];
    }
    store_hl16i(g_khl + (size_t)row * 8, rv);

    // v
#pragma unroll
    for (int o = 0; o < 32; o++) {
        float acc = s_bv[o];
#pragma unroll
        for (int c = 0; c < 32; c++) acc = fmaf(s_wv[o * 32 + c], xcd[c], acc);
        store_v(g_vp + (size_t)(ab * 32 + o) * (NP * 2), p, acc);
    }
}

// ---------------- K4: split-K, shift-free FA mma.sync attention ----------------
__device__ __forceinline__ void stage_tile(const char* gk, const char* gv,
                                           uint32_t skb, uint32_t svb,
                                           int tid, int tile, int buf) {
    const char* ks = gk + (size_t)tile * 8192;
    uint32_t kd = skb + (uint32_t)buf * 8192;
#pragma unroll
    for (int n = 0; n < 4; n++) {
        uint32_t off = (uint32_t)(tid + n * 128) * 16;
        uint32_t key = off >> 6;
        cpa16(kd + (off ^ ((key & 3) << 5)), ks + off);
    }
    const char* vs = gv + (size_t)tile * 256;
    uint32_t vd = svb + (uint32_t)buf * 8192;
#pragma unroll
    for (int n = 0; n < 4; n++) {
        int w = tid + n * 128;
        int ch = w >> 4, wi = w & 15;
        uint32_t off = (uint32_t)(ch * 256 + wi * 16);
        cpa16(vd + (off ^ (((uint32_t)ch & 3) << 5)), vs + (size_t)ch * (NP * 2) + wi * 16);
    }
}

__global__ __launch_bounds__(128) void k_attn() {
    __shared__ __align__(128) char sKs[2][8192];
    __shared__ __align__(128) char sVs[2][8192];
    int z = blockIdx.z;                  // a*2 + split
    int a = z >> 1, sp = z & 1;
    int b = blockIdx.y;
    int ab = a * NB + b;
    int tid = threadIdx.x;
    int wid = tid >> 5, lane = tid & 31;
    int g = lane >> 2, t = lane & 3;
    int q0 = blockIdx.x * 64 + wid * 16;

    const u64* QHL = g_qhl + (size_t)ab * NP * 8;
    const char* gk = (const char*)(g_khl + (size_t)ab * NP * 8);
    const char* gv = g_vp + (size_t)ab * 32 * (NP * 2);

    uint32_t skb = smem_u32(sKs);
    uint32_t svb = smem_u32(sVs);
    uint32_t swz = ((uint32_t)g & 3) << 5;

    uint32_t qh[4], ql[4];
    {
        int r0 = q0 + g, r1 = r0 + 8;
        u64 w0 = QHL[r0 * 8 + t];
        u64 w1 = QHL[r1 * 8 + t];
        u64 w2 = QHL[r0 * 8 + t + 4];
        u64 w3 = QHL[r1 * 8 + t + 4];
        qh[0] = (uint32_t)w0; ql[0] = (uint32_t)(w0 >> 32);
        qh[1] = (uint32_t)w1; ql[1] = (uint32_t)(w1 >> 32);
        qh[2] = (uint32_t)w2; ql[2] = (uint32_t)(w2 >> 32);
        qh[3] = (uint32_t)w3; ql[3] = (uint32_t)(w3 >> 32);
    }

    float oacc[16];
#pragma unroll
    for (int i = 0; i < 16; i++) oacc[i] = 0.0f;
    float ls0 = 0.0f, ls1 = 0.0f;

    const int tile0 = sp * (NKT / 2);
    stage_tile(gk, gv, skb, svb, tid, tile0, 0);
    CP_COMMIT();

    for (int kk = 0; kk < NKT / 2; kk++) {
        int buf = kk & 1;
        if (kk + 1 < NKT / 2) {
            stage_tile(gk, gv, skb, svb, tid, tile0 + kk + 1, (kk + 1) & 1);
            CP_COMMIT();
            CP_WAIT1();
        } else {
            CP_WAIT0();
        }
        __syncthreads();

        uint32_t kb = skb + (uint32_t)buf * 8192;
        uint32_t vbb = svb + (uint32_t)buf * 8192;

#pragma unroll
        for (int half = 0; half < 2; half++) {
            float acc[8][4];
#pragma unroll
            for (int j = 0; j < 8; j++) {
                acc[j][0] = acc[j][1] = acc[j][2] = acc[j][3] = 0.0f;
            }
#pragma unroll
            for (int j = 0; j < 8; j++) {
                uint32_t row = (uint32_t)(half * 64 + 8 * j + g) * 64 + (uint32_t)t * 8;
                uint32_t a0 = kb + (row ^ swz);
                uint32_t a1 = kb + ((row + 32) ^ swz);
                uint32_t b0h, b0l, b1h, b1l;
                asm("ld.shared.v2.b32 {%0,%1}, [%2];" : "=r"(b0h), "=r"(b0l) : "r"(a0));
                asm("ld.shared.v2.b32 {%0,%1}, [%2];" : "=r"(b1h), "=r"(b1l) : "r"(a1));
                mma_bf16(acc[j], qh, b0h, b1h);
                mma_bf16(acc[j], ql, b0h, b1h);
                mma_bf16(acc[j], qh, b0l, b1l);
            }
#pragma unroll
            for (int kc = 0; kc < 4; kc++) {
                float p0 = ex2f(acc[2 * kc][0]);
                float p1 = ex2f(acc[2 * kc][1]);
                float p2 = ex2f(acc[2 * kc][2]);
                float p3 = ex2f(acc[2 * kc][3]);
                float p4 = ex2f(acc[2 * kc + 1][0]);
                float p5 = ex2f(acc[2 * kc + 1][1]);
                float p6 = ex2f(acc[2 * kc + 1][2]);
                float p7 = ex2f(acc[2 * kc + 1][3]);
                ls0 += (p0 + p1) + (p4 + p5);
                ls1 += (p2 + p3) + (p6 + p7);
                uint32_t pa[4] = { pkbf2(p0, p1), pkbf2(p2, p3), pkbf2(p4, p5), pkbf2(p6, p7) };
#pragma unroll
                for (int j2 = 0; j2 < 4; j2++) {
                    uint32_t off = (uint32_t)((8 * j2 + g) * 256 + (half * 4 + kc) * 32 + t * 8);
                    uint32_t addr = vbb + (off ^ swz);
                    uint32_t vb0, vb1;
                    asm("ld.shared.v2.b32 {%0,%1}, [%2];" : "=r"(vb0), "=r"(vb1) : "r"(addr));
                    mma_bf16(&oacc[4 * j2], pa, vb0, vb1);
                }
            }
        }
        __syncthreads();
    }

    float l0 = ls0;
    l0 += __shfl_xor_sync(0xffffffffu, l0, 1);
    l0 += __shfl_xor_sync(0xffffffffu, l0, 2);
    float l1 = ls1;
    l1 += __shfl_xor_sync(0xffffffffu, l1, 1);
    l1 += __shfl_xor_sync(0xffffffffu, l1, 2);

    float* pO = g_pacc + (size_t)(ab * 2 + sp) * 32 * NP;
    float* pL = g_pl + (ab * 2 + sp) * NP;
    int r0 = q0 + g, r1 = r0 + 8;
#pragma unroll
    for (int j2 = 0; j2 < 4; j2++) {
        int ch = 8 * j2 + 2 * t;
        pO[ch * NP + r0]       = oacc[4 * j2 + 0];
        pO[(ch + 1) * NP + r0] = oacc[4 * j2 + 1];
        pO[ch * NP + r1]       = oacc[4 * j2 + 2];
        pO[(ch + 1) * NP + r1] = oacc[4 * j2 + 3];
    }
    if (t == 0) { pL[r0] = l0; pL[r1] = l1; }
}

// ---------------- K5: split-K reduce + normalize + GN partial stats ----------------
__global__ __launch_bounds__(256) void k_statsnorm() {
    int gb = blockIdx.x >> 3;            // ab
    int ch = blockIdx.x & 7;             // chunk (covers 4 channels)
    const float* pa0 = g_pacc + (size_t)(gb * 2 + 0) * 32 * NP + ch * (NTOT / 8);
    const float* pa1 = g_pacc + (size_t)(gb * 2 + 1) * 32 * NP + ch * (NTOT / 8);
    const float* pl0 = g_pl + (gb * 2 + 0) * NP;
    const float* pl1 = g_pl + (gb * 2 + 1) * NP;
    float* dst = g_ao[gb >> 1] + (gb & 1) * 32 * NP + ch * (NTOT / 8);

    float s1 = 0.0f;
    double s2 = 0.0;
    for (int i = threadIdx.x; i < NTOT / 8; i += 256) {
        int q = i % NP;                  // chunk base is a multiple of NP
        float v = __fdividef(pa0[i] + pa1[i], pl0[q] + pl1[q]);
        dst[i] = v;
        s1 += v;
        s2 += (double)v * (double)v;
    }
    __shared__ float  r1[256];
    __shared__ double r2[256];
    r1[threadIdx.x] = s1; r2[threadIdx.x] = s2;
    __syncthreads();
    for (int s = 128; s > 0; s >>= 1) {
        if (threadIdx.x < s) { r1[threadIdx.x] += r1[threadIdx.x + s]; r2[threadIdx.x] += r2[threadIdx.x + s]; }
        __syncthreads();
    }
    if (threadIdx.x == 0) {
        g_psum[gb][ch][0] = (double)r1[0];
        g_psum[gb][ch][1] = r2[0];
    }
}

// ---------------- K6: groupnorm apply + up conv 32 -> 64 ----------------
__global__ __launch_bounds__(128) void k_gnup(
    const float* __restrict__ gnw,  const float* __restrict__ gnb,
    const float* __restrict__ gnws, const float* __restrict__ gnbs,
    const float* __restrict__ wup,  const float* __restrict__ bup,
    const float* __restrict__ wups, const float* __restrict__ bups) {
    int a = blockIdx.z, b = blockIdx.y;
    int gb = a * 2 + b;
    __shared__ float sw[64 * 32];
    __shared__ float sb2[64], sa_[32], sd_[32];
    const float* w   = a ? wups : wup;
    const float* bb  = a ? bups : bup;
    const float* gw  = a ? gnws : gnw;
    const float* gbb = a ? gnbs : gnb;
    double s1 = 0.0, s2 = 0.0;
#pragma unroll
    for (int c = 0; c < 8; c++) { s1 += g_psum[gb][c][0]; s2 += g_psum[gb][c][1]; }
    double mu_d  = s1 / (double)NTOT;
    double var_d = s2 / (double)NTOT - mu_d * mu_d;
    float mu = (float)mu_d;
    float rstd = rsqrtf((float)var_d + 1e-5f);
    for (int i = threadIdx.x; i < 2048; i += 128) sw[i] = w[i];
    if (threadIdx.x < 64) sb2[threadIdx.x] = bb[threadIdx.x];
    if (threadIdx.x < 32) {
        float aa = rstd * gw[threadIdx.x];
        sa_[threadIdx.x] = aa;
        sd_[threadIdx.x] = gbb[threadIdx.x] - mu * aa;
    }
    __syncthreads();
    int p = blockIdx.x * 128 + threadIdx.x;
    const float* src = g_ao[a] + b * 32 * NP;
    float xn[32];
#pragma unroll
    for (int c = 0; c < 32; c++) xn[c] = fmaf(src[c * NP + p], sa_[c], sd_[c]);
    float* dst = g_up[a] + b * 64 * NP;
#pragma unroll
    for (int o = 0; o < 64; o++) {
        float acc = sb2[o];
#pragma unroll
        for (int c = 0; c < 32; c++) acc = fmaf(sw[o * 32 + c], xn[c], acc);
        dst[o * NP + p] = acc;
    }
}

// ---------------- K7: upsample + combine ----------------
__device__ __forceinline__ float tri8(const float* __restrict__ s,
                                      int p00, int p01, int p10, int p11,
                                      int w0, int w1, float ww, float wh, float wt) {
    float c00 = s[p00 + w0]; c00 += (s[p00 + w1] - c00) * ww;
    float c01 = s[p01 + w0]; c01 += (s[p01 + w1] - c01) * ww;
    float c10 = s[p10 + w0]; c10 += (s[p10 + w1] - c10) * ww;
    float c11 = s[p11 + w0]; c11 += (s[p11 + w1] - c11) * ww;
    float c0 = c00 + (c01 - c00) * wh;
    float c1 = c10 + (c11 - c10) * wh;
    return c0 + (c1 - c0) * wt;
}

__global__ void k_final(const float* __restrict__ xc, float* __restrict__ out) {
    int idx = blockIdx.x * 256 + threadIdx.x;
    int w = idx % WF;
    int h = (idx / WF) % HF;
    int t = (idx / (WF * HF)) % TF;
    int bc = idx / (WF * HF * TF);

    float pt = (float)t * (7.0f / 15.0f);
    int t0 = (int)pt; float wt = pt - (float)t0; int t1 = min(t0 + 1, 7); t0 = min(t0, 7);
    float ph = (float)h * (23.0f / 47.0f);
    int h0 = (int)ph; float wh = ph - (float)h0; int h1 = min(h0 + 1, 23); h0 = min(h0, 23);
    float pw = (float)w * (23.0f / 47.0f);
    int w0 = (int)pw; float ww = pw - (float)w0; int w1 = min(w0 + 1, 23); w0 = min(w0, 23);

    int base = bc * NP;
    int p00 = t0 * (HHd * WWd) + h0 * WWd;
    int p01 = t0 * (HHd * WWd) + h1 * WWd;
    int p10 = t1 * (HHd * WWd) + h0 * WWd;
    int p11 = t1 * (HHd * WWd) + h1 * WWd;

    float r_cross = tri8(g_up[0] + base, p00, p01, p10, p11, w0, w1, ww, wh, wt);
    float r_self  = tri8(g_up[1] + base, p00, p01, p10, p11, w0, w1, ww, wh, wt);
    out[idx] = r_self + xc[idx] - 0.5f * r_cross;
}

// ---------------- launch ----------------
extern "C" void kernel_launch(void* const* d_in, const int* in_sizes, int n_in,
                              void* d_out, int out_size) {
    const float* x       = (const float*)d_in[0];
    const float* x_c     = (const float*)d_in[1];
    const float* w_down  = (const float*)d_in[2];
    const float* b_down  = (const float*)d_in[3];
    const float* w_downc = (const float*)d_in[4];
    const float* b_downc = (const float*)d_in[5];
    const float* w_q     = (const float*)d_in[6];
    const float* b_q     = (const float*)d_in[7];
    const float* w_k     = (const float*)d_in[8];
    const float* b_k     = (const float*)d_in[9];
    const float* w_v     = (const float*)d_in[10];
    const float* b_v     = (const float*)d_in[11];
    const float* w_qsa   = (const float*)d_in[12];
    const float* b_qsa   = (const float*)d_in[13];
    const float* w_ksa   = (const float*)d_in[14];
    const float* b_ksa   = (const float*)d_in[15];
    const float* w_vsa   = (const float*)d_in[16];
    const float* b_vsa   = (const float*)d_in[17];
    const float* gn_w    = (const float*)d_in[18];
    const float* gn_b    = (const float*)d_in[19];
    const float* gn_wsa  = (const float*)d_in[20];
    const float* gn_bsa  = (const float*)d_in[21];
    const float* w_up    = (const float*)d_in[22];
    const float* b_up    = (const float*)d_in[23];
    const float* w_upsa  = (const float*)d_in[24];
    const float* b_upsa  = (const float*)d_in[25];
    const float* offset  = (const float*)d_in[26];
    const float* offsetc = (const float*)d_in[27];

    dim3 g1(2304, 1, 2);
    k_resize<<<g1, 256>>>(x, x_c);

    dim3 g2(72, 1, 2);
    k_down<<<g2, 128>>>(w_down, b_down, w_downc, b_downc);

    dim3 g3(72, 1, 2);
    k_proj<<<g3, 128>>>(w_q, b_q, w_k, b_k, w_v, b_v,
                        w_qsa, b_qsa, w_ksa, b_ksa, w_vsa, b_vsa,
                        offset, offsetc);

    dim3 g4(72, NB, 4);
    k_attn<<<g4, 128>>>();

    k_statsnorm<<<32, 256>>>();

    dim3 g6(36, NB, 2);
    k_gnup<<<g6, 128>>>(gn_w, gn_b, gn_wsa, gn_bsa, w_up, b_up, w_upsa, b_upsa);

    k_final<<<18432, 256>>>(x_c, (float*)d_out);
}

// round 12
// speedup vs baseline: 1.0662x; 1.0662x over previous
#include <cuda_runtime.h>
#include <cuda_bf16.h>
#include <cstdint>

// ---------------- constants ----------------
#define NB    2
#define CIN   64
#define CD    32
#define HHd   24
#define WWd   24
#define NP    4608          // 8*24*24
#define TF    16
#define HF    48
#define WF    48
#define NTOT  (32*NP)
#define KT    128
#define NKT   (NP/KT)       // 36
#define QSCALE 0.72134752044482f   // 0.5 * log2(e): scores land in log2 domain

typedef unsigned long long u64;

// ---------------- scratch ----------------
__device__ float g_xr [NB*CIN*NP];
__device__ float g_xcr[NB*CIN*NP];
__device__ float g_xd [NB*CD*NP];
__device__ float g_xcd[NB*CD*NP];
// Q/K: per row 8 u64 slots, reordered: pos 2t   = old slot t   (lo32 hi-pair, hi32 lo-pair)
//                                      pos 2t+1 = old slot t+4
__device__ __align__(16) u64 g_qhl[2*NB*NP*8];
__device__ __align__(16) u64 g_khl[2*NB*NP*8];
// V: per (ab,ch): NP/16 groups x 32B; group block: slot t(8B) = {pair(16g+2t,+1), pair(16g+2t+8,+9)}
__device__ __align__(16) char g_vp[(size_t)2*NB*32*NP*2];
__device__ float g_pacc[2*NB*2*32*NP];   // split-K unnormalized O partials
__device__ float g_pl  [2*NB*2*NP];      // split-K l partials
__device__ float g_ao [2][NB*32*NP];
__device__ float g_up [2][NB*64*NP];
__device__ double g_psum[4][32][2];

// ---------------- helpers ----------------
__device__ __forceinline__ uint32_t smem_u32(const void* p) {
    uint32_t a;
    asm("{ .reg .u64 t; cvta.to.shared.u64 t, %1; cvt.u32.u64 %0, t; }" : "=r"(a) : "l"(p));
    return a;
}
__device__ __forceinline__ uint32_t pkb(__nv_bfloat16 lo, __nv_bfloat16 hi) {
    return ((uint32_t)__bfloat16_as_ushort(hi) << 16) | (uint32_t)__bfloat16_as_ushort(lo);
}
__device__ __forceinline__ uint32_t pkbf2(float lo, float hi) {
    uint32_t r;
    asm("cvt.rn.bf16x2.f32 %0, %1, %2;" : "=r"(r) : "f"(hi), "f"(lo));
    return r;
}
__device__ __forceinline__ float ex2f(float x) {
    float r;
    asm("ex2.approx.f32 %0, %1;" : "=f"(r) : "f"(x));
    return r;
}
__device__ __forceinline__ void mma_bf16(float* c, const uint32_t* a, uint32_t b0, uint32_t b1) {
    asm volatile(
        "mma.sync.aligned.m16n8k16.row.col.f32.bf16.bf16.f32 "
        "{%0,%1,%2,%3}, {%4,%5,%6,%7}, {%8,%9}, {%0,%1,%2,%3};"
        : "+f"(c[0]), "+f"(c[1]), "+f"(c[2]), "+f"(c[3])
        : "r"(a[0]), "r"(a[1]), "r"(a[2]), "r"(a[3]), "r"(b0), "r"(b1));
}
__device__ __forceinline__ void cpa16(uint32_t dst, const void* src) {
    asm volatile("cp.async.cg.shared.global [%0], [%1], 16;" :: "r"(dst), "l"(src) : "memory");
}
#define CP_COMMIT() asm volatile("cp.async.commit_group;" ::: "memory")
#define CP_WAIT1()  asm volatile("cp.async.wait_group 1;" ::: "memory")
#define CP_WAIT0()  asm volatile("cp.async.wait_group 0;" ::: "memory")

// ---------------- K1: trilinear downsample ----------------
__global__ void k_resize(const float* __restrict__ x, const float* __restrict__ xc) {
    int i = blockIdx.x * 256 + threadIdx.x;
    const float* src = blockIdx.z ? xc : x;
    float* dst = blockIdx.z ? g_xcr : g_xr;
    int p  = i % NP;
    int bc = i / NP;
    int w = p % WWd, h = (p / WWd) % HHd, t = p / (WWd * HHd);

    float pt = (float)t * (15.0f / 7.0f);
    int t0 = (int)pt; float wt = pt - (float)t0; int t1 = min(t0 + 1, 15); t0 = min(t0, 15);
    float ph = (float)h * (47.0f / 23.0f);
    int h0 = (int)ph; float wh = ph - (float)h0; int h1 = min(h0 + 1, 47); h0 = min(h0, 47);
    float pw = (float)w * (47.0f / 23.0f);
    int w0 = (int)pw; float ww = pw - (float)w0; int w1 = min(w0 + 1, 47); w0 = min(w0, 47);

    const float* base = src + (size_t)bc * (TF * HF * WF);
#define ATI(ti,hi,wi) __ldg(base + (ti)*(HF*WF) + (hi)*WF + (wi))
    float c00 = ATI(t0,h0,w0); c00 += (ATI(t0,h0,w1) - c00) * ww;
    float c01 = ATI(t0,h1,w0); c01 += (ATI(t0,h1,w1) - c01) * ww;
    float c10 = ATI(t1,h0,w0); c10 += (ATI(t1,h0,w1) - c10) * ww;
    float c11 = ATI(t1,h1,w0); c11 += (ATI(t1,h1,w1) - c11) * ww;
#undef ATI
    float c0 = c00 + (c01 - c00) * wh;
    float c1 = c10 + (c11 - c10) * wh;
    dst[i] = c0 + (c1 - c0) * wt;
}

// ---------------- K2: down conv 64 -> 32 ----------------
__global__ __launch_bounds__(128) void k_down(
    const float* __restrict__ wd, const float* __restrict__ bd,
    const float* __restrict__ wdc, const float* __restrict__ bdc) {
    __shared__ float sw[CD * CIN];
    __shared__ float sb[CD];
    const float* w  = blockIdx.z ? wdc : wd;
    const float* bb = blockIdx.z ? bdc : bd;
    const float* in = blockIdx.z ? g_xcr : g_xr;
    float* out      = blockIdx.z ? g_xcd : g_xd;
    for (int i = threadIdx.x; i < CD * CIN; i += 128) sw[i] = w[i];
    if (threadIdx.x < CD) sb[threadIdx.x] = bb[threadIdx.x];
    __syncthreads();
    int idx = blockIdx.x * 128 + threadIdx.x;
    int b = idx / NP, p = idx % NP;
    float xin[CIN];
#pragma unroll
    for (int c = 0; c < CIN; c++) xin[c] = in[(b * CIN + c) * NP + p];
#pragma unroll
    for (int o = 0; o < CD; o++) {
        float acc = sb[o];
#pragma unroll
        for (int c = 0; c < CIN; c++) acc = fmaf(sw[o * CIN + c], xin[c], acc);
        out[(b * CD + o) * NP + p] = acc;
    }
}

// ---------------- K3: QKV projections + RoPE -> packed layouts ----------------
// slot i (channel pair 2i,2i+1) -> memory position ((i&3)<<1) | (i>>2)
__device__ __forceinline__ void store_hl16i(u64* d, const float* v) {
#pragma unroll
    for (int i = 0; i < 8; i++) {
        float v0 = v[2 * i], v1 = v[2 * i + 1];
        __nv_bfloat16 h0 = __float2bfloat16(v0);
        __nv_bfloat16 h1 = __float2bfloat16(v1);
        __nv_bfloat16 e0 = __float2bfloat16(v0 - __bfloat162float(h0));
        __nv_bfloat16 e1 = __float2bfloat16(v1 - __bfloat162float(h1));
        d[((i & 3) << 1) | (i >> 2)] = ((u64)pkb(e0, e1) << 32) | (u64)pkb(h0, h1);
    }
}
__device__ __forceinline__ void store_v(char* base_ab_ch, int p, float val) {
    int gi = p >> 4, r = p & 15;
    int ofs = ((r & 7) >> 1) * 8 + ((r >> 3) & 1) * 4 + (r & 1) * 2;
    *(__nv_bfloat16*)(base_ab_ch + (size_t)gi * 32 + ofs) = __float2bfloat16(val);
}

// z = 0: q,k,v (attn 0) ; z = 1: q_sa,k_sa,v_sa (attn 1)
__global__ __launch_bounds__(128) void k_proj(
    const float* __restrict__ wq,  const float* __restrict__ bq,
    const float* __restrict__ wk,  const float* __restrict__ bk,
    const float* __restrict__ wv,  const float* __restrict__ bv,
    const float* __restrict__ wqs, const float* __restrict__ bqs,
    const float* __restrict__ wks, const float* __restrict__ bks,
    const float* __restrict__ wvs, const float* __restrict__ bvs,
    const float* __restrict__ off, const float* __restrict__ offc) {
    int z = blockIdx.z;
    __shared__ float s_wq[512], s_wk[512], s_wv[1024];
    __shared__ float s_bq[16], s_bk[16], s_bv[32];
    {
        const float* WQ = z ? wqs : wq;
        const float* WK = z ? wks : wk;
        const float* WV = z ? wvs : wv;
        const float* BQ = z ? bqs : bq;
        const float* BK = z ? bks : bk;
        const float* BV = z ? bvs : bv;
        for (int i = threadIdx.x; i < 512; i += 128) { s_wq[i] = WQ[i]; s_wk[i] = WK[i]; }
        for (int i = threadIdx.x; i < 1024; i += 128) s_wv[i] = WV[i];
        if (threadIdx.x < 16) { s_bq[threadIdx.x] = BQ[threadIdx.x]; s_bk[threadIdx.x] = BK[threadIdx.x]; }
        if (threadIdx.x < 32) s_bv[threadIdx.x] = BV[threadIdx.x];
    }
    __syncthreads();

    int idx = blockIdx.x * 128 + threadIdx.x;
    int b = idx / NP, p = idx % NP, t = p / (HHd * WWd);
    int ab = z * NB + b;

    float xq[32], xcd[32];
#pragma unroll
    for (int c = 0; c < 32; c++) xcd[c] = g_xcd[(b * 32 + c) * NP + p];
    if (z == 0) {
#pragma unroll
        for (int c = 0; c < 32; c++) xq[c] = g_xd[(b * 32 + c) * NP + p];
    } else {
#pragma unroll
        for (int c = 0; c < 32; c++) xq[c] = xcd[c];
    }

    const float invf[8] = {1.0f, 0.31622776601683794f, 0.1f, 0.031622776601683794f,
                           0.01f, 0.0031622776601683794f, 0.001f, 0.00031622776601683794f};
    float se[8], ce[8], sk_[8], ck_[8];
    float tf = (float)t;
#pragma unroll
    for (int i = 0; i < 8; i++) {
        float a = tf * invf[i];
        float s = sinf(a), c = cosf(a);
        float o1 = off[i * 500 + t];             // q rope offset (both attns use `offset`)
        se[i] = s + o1; ce[i] = c + o1;          // same offset on sin AND cos (per reference)
        if (z == 0) {
            float o2 = offc[i * 500 + t];        // cross-attn k uses offset_c
            sk_[i] = s + o2; ck_[i] = c + o2;
        } else {
            sk_[i] = se[i]; ck_[i] = ce[i];      // self-attn k uses offset
        }
    }

    float tmp[16], rv[16];
    int row = ab * NP + p;

    // q = rope(Wq*xq + bq) * (0.5*log2e)  -> scores in log2 domain for ex2.approx
#pragma unroll
    for (int o = 0; o < 16; o++) {
        float acc = s_bq[o];
#pragma unroll
        for (int c = 0; c < 32; c++) acc = fmaf(s_wq[o * 32 + c], xq[c], acc);
        tmp[o] = acc;
    }
#pragma unroll
    for (int i = 0; i < 8; i++) {
        rv[i]     = QSCALE * (tmp[i] * ce[i] - tmp[8 + i] * se[i]);
        rv[8 + i] = QSCALE * (tmp[8 + i] * ce[i] + tmp[i] * se[i]);
    }
    store_hl16i(g_qhl + (size_t)row * 8, rv);

    // k = rope(Wk*xcd + bk)
#pragma unroll
    for (int o = 0; o < 16; o++) {
        float acc = s_bk[o];
#pragma unroll
        for (int c = 0; c < 32; c++) acc = fmaf(s_wk[o * 32 + c], xcd[c], acc);
        tmp[o] = acc;
    }
#pragma unroll
    for (int i = 0; i < 8; i++) {
        rv[i]     = tmp[i] * ck_[i] - tmp[8 + i] * sk_[i];
        rv[8 + i] = tmp[8 + i] * ck_[i] + tmp[i] * sk_[i];
    }
    store_hl16i(g_khl + (size_t)row * 8, rv);

    // v
#pragma unroll
    for (int o = 0; o < 32; o++) {
        float acc = s_bv[o];
#pragma unroll
        for (int c = 0; c < 32; c++) acc = fmaf(s_wv[o * 32 + c], xcd[c], acc);
        store_v(g_vp + (size_t)(ab * 32 + o) * (NP * 2), p, acc);
    }
}

// ---------------- K4: split-K, shift-free FA mma.sync attention ----------------
__device__ __forceinline__ void stage_tile(const char* gk, const char* gv,
                                           uint32_t skb, uint32_t svb,
                                           int tid, int tile, int buf) {
    const char* ks = gk + (size_t)tile * 8192;
    uint32_t kd = skb + (uint32_t)buf * 8192;
#pragma unroll
    for (int n = 0; n < 4; n++) {
        uint32_t off = (uint32_t)(tid + n * 128) * 16;
        uint32_t key = off >> 6;
        cpa16(kd + (off ^ ((key & 3) << 5)), ks + off);
    }
    const char* vs = gv + (size_t)tile * 256;
    uint32_t vd = svb + (uint32_t)buf * 8192;
#pragma unroll
    for (int n = 0; n < 4; n++) {
        int w = tid + n * 128;
        int ch = w >> 4, wi = w & 15;
        uint32_t off = (uint32_t)(ch * 256 + wi * 16);
        cpa16(vd + (off ^ (((uint32_t)ch & 3) << 5)), vs + (size_t)ch * (NP * 2) + wi * 16);
    }
}

__global__ __launch_bounds__(128) void k_attn() {
    __shared__ __align__(128) char sKs[2][8192];
    __shared__ __align__(128) char sVs[2][8192];
    int z = blockIdx.z;                  // a*2 + split
    int a = z >> 1, sp = z & 1;
    int b = blockIdx.y;
    int ab = a * NB + b;
    int tid = threadIdx.x;
    int wid = tid >> 5, lane = tid & 31;
    int g = lane >> 2, t = lane & 3;
    int q0 = blockIdx.x * 64 + wid * 16;

    const u64* QHL = g_qhl + (size_t)ab * NP * 8;
    const char* gk = (const char*)(g_khl + (size_t)ab * NP * 8);
    const char* gv = g_vp + (size_t)ab * 32 * (NP * 2);

    uint32_t skb = smem_u32(sKs);
    uint32_t svb = smem_u32(sVs);
    uint32_t swz = ((uint32_t)g & 3) << 5;

    uint32_t qh[4], ql[4];
    {
        int r0 = q0 + g, r1 = r0 + 8;
        u64 w0 = QHL[r0 * 8 + 2 * t];         // old slot t
        u64 w2 = QHL[r0 * 8 + 2 * t + 1];     // old slot t+4
        u64 w1 = QHL[r1 * 8 + 2 * t];
        u64 w3 = QHL[r1 * 8 + 2 * t + 1];
        qh[0] = (uint32_t)w0; ql[0] = (uint32_t)(w0 >> 32);
        qh[1] = (uint32_t)w1; ql[1] = (uint32_t)(w1 >> 32);
        qh[2] = (uint32_t)w2; ql[2] = (uint32_t)(w2 >> 32);
        qh[3] = (uint32_t)w3; ql[3] = (uint32_t)(w3 >> 32);
    }

    float oacc[16];
#pragma unroll
    for (int i = 0; i < 16; i++) oacc[i] = 0.0f;
    float ls0 = 0.0f, ls1 = 0.0f;

    const int tile0 = sp * (NKT / 2);
    stage_tile(gk, gv, skb, svb, tid, tile0, 0);
    CP_COMMIT();

    for (int kk = 0; kk < NKT / 2; kk++) {
        int buf = kk & 1;
        if (kk + 1 < NKT / 2) {
            stage_tile(gk, gv, skb, svb, tid, tile0 + kk + 1, (kk + 1) & 1);
            CP_COMMIT();
            CP_WAIT1();
        } else {
            CP_WAIT0();
        }
        __syncthreads();

        uint32_t kb = skb + (uint32_t)buf * 8192;
        uint32_t vbb = svb + (uint32_t)buf * 8192;

#pragma unroll
        for (int half = 0; half < 2; half++) {
            float acc[8][4];
#pragma unroll
            for (int j = 0; j < 8; j++) {
                acc[j][0] = acc[j][1] = acc[j][2] = acc[j][3] = 0.0f;
            }
#pragma unroll
            for (int j = 0; j < 8; j++) {
                uint32_t row = (uint32_t)(half * 64 + 8 * j + g) * 64 + (uint32_t)t * 16;
                uint32_t addr = kb + (row ^ swz);
                uint32_t b0h, b0l, b1h, b1l;
                asm("ld.shared.v4.b32 {%0,%1,%2,%3}, [%4];"
                    : "=r"(b0h), "=r"(b0l), "=r"(b1h), "=r"(b1l) : "r"(addr));
                mma_bf16(acc[j], qh, b0h, b1h);
                mma_bf16(acc[j], ql, b0h, b1h);
                mma_bf16(acc[j], qh, b0l, b1l);
            }
#pragma unroll
            for (int kc = 0; kc < 4; kc++) {
                float p0 = ex2f(acc[2 * kc][0]);
                float p1 = ex2f(acc[2 * kc][1]);
                float p2 = ex2f(acc[2 * kc][2]);
                float p3 = ex2f(acc[2 * kc][3]);
                float p4 = ex2f(acc[2 * kc + 1][0]);
                float p5 = ex2f(acc[2 * kc + 1][1]);
                float p6 = ex2f(acc[2 * kc + 1][2]);
                float p7 = ex2f(acc[2 * kc + 1][3]);
                ls0 += (p0 + p1) + (p4 + p5);
                ls1 += (p2 + p3) + (p6 + p7);
                uint32_t pa[4] = { pkbf2(p0, p1), pkbf2(p2, p3), pkbf2(p4, p5), pkbf2(p6, p7) };
#pragma unroll
                for (int j2 = 0; j2 < 4; j2++) {
                    uint32_t off = (uint32_t)((8 * j2 + g) * 256 + (half * 4 + kc) * 32 + t * 8);
                    uint32_t addr = vbb + (off ^ swz);
                    uint32_t vb0, vb1;
                    asm("ld.shared.v2.b32 {%0,%1}, [%2];" : "=r"(vb0), "=r"(vb1) : "r"(addr));
                    mma_bf16(&oacc[4 * j2], pa, vb0, vb1);
                }
            }
        }
        __syncthreads();
    }

    float l0 = ls0;
    l0 += __shfl_xor_sync(0xffffffffu, l0, 1);
    l0 += __shfl_xor_sync(0xffffffffu, l0, 2);
    float l1 = ls1;
    l1 += __shfl_xor_sync(0xffffffffu, l1, 1);
    l1 += __shfl_xor_sync(0xffffffffu, l1, 2);

    float* pO = g_pacc + (size_t)(ab * 2 + sp) * 32 * NP;
    float* pL = g_pl + (ab * 2 + sp) * NP;
    int r0 = q0 + g, r1 = r0 + 8;
#pragma unroll
    for (int j2 = 0; j2 < 4; j2++) {
        int ch = 8 * j2 + 2 * t;
        pO[ch * NP + r0]       = oacc[4 * j2 + 0];
        pO[(ch + 1) * NP + r0] = oacc[4 * j2 + 1];
        pO[ch * NP + r1]       = oacc[4 * j2 + 2];
        pO[(ch + 1) * NP + r1] = oacc[4 * j2 + 3];
    }
    if (t == 0) { pL[r0] = l0; pL[r1] = l1; }
}

// ---------------- K5: split-K reduce + normalize + GN partial stats (128 blocks) ----------------
__global__ __launch_bounds__(256) void k_statsnorm() {
    int gb = blockIdx.x >> 5;            // ab
    int c  = blockIdx.x & 31;            // channel
    const float* pa0 = g_pacc + (size_t)(gb * 2 + 0) * 32 * NP + c * NP;
    const float* pa1 = g_pacc + (size_t)(gb * 2 + 1) * 32 * NP + c * NP;
    const float* pl0 = g_pl + (gb * 2 + 0) * NP;
    const float* pl1 = g_pl + (gb * 2 + 1) * NP;
    float* dst = g_ao[gb >> 1] + (gb & 1) * 32 * NP + c * NP;

    float s1 = 0.0f;
    double s2 = 0.0;
    for (int i = threadIdx.x; i < NP; i += 256) {
        float v = __fdividef(pa0[i] + pa1[i], pl0[i] + pl1[i]);
        dst[i] = v;
        s1 += v;
        s2 += (double)v * (double)v;
    }
    __shared__ float  r1[256];
    __shared__ double r2[256];
    r1[threadIdx.x] = s1; r2[threadIdx.x] = s2;
    __syncthreads();
    for (int s = 128; s > 0; s >>= 1) {
        if (threadIdx.x < s) { r1[threadIdx.x] += r1[threadIdx.x + s]; r2[threadIdx.x] += r2[threadIdx.x + s]; }
        __syncthreads();
    }
    if (threadIdx.x == 0) {
        g_psum[gb][c][0] = (double)r1[0];
        g_psum[gb][c][1] = r2[0];
    }
}

// ---------------- K6: groupnorm apply + up conv 32 -> 64 ----------------
__global__ __launch_bounds__(128) void k_gnup(
    const float* __restrict__ gnw,  const float* __restrict__ gnb,
    const float* __restrict__ gnws, const float* __restrict__ gnbs,
    const float* __restrict__ wup,  const float* __restrict__ bup,
    const float* __restrict__ wups, const float* __restrict__ bups) {
    int a = blockIdx.z, b = blockIdx.y;
    int gb = a * 2 + b;
    __shared__ float sw[64 * 32];
    __shared__ float sb2[64], sa_[32], sd_[32];
    const float* w   = a ? wups : wup;
    const float* bb  = a ? bups : bup;
    const float* gw  = a ? gnws : gnw;
    const float* gbb = a ? gnbs : gnb;
    double s1 = 0.0, s2 = 0.0;
#pragma unroll
    for (int c = 0; c < 32; c++) { s1 += g_psum[gb][c][0]; s2 += g_psum[gb][c][1]; }
    double mu_d  = s1 / (double)NTOT;
    double var_d = s2 / (double)NTOT - mu_d * mu_d;
    float mu = (float)mu_d;
    float rstd = rsqrtf((float)var_d + 1e-5f);
    for (int i = threadIdx.x; i < 2048; i += 128) sw[i] = w[i];
    if (threadIdx.x < 64) sb2[threadIdx.x] = bb[threadIdx.x];
    if (threadIdx.x < 32) {
        float aa = rstd * gw[threadIdx.x];
        sa_[threadIdx.x] = aa;
        sd_[threadIdx.x] = gbb[threadIdx.x] - mu * aa;
    }
    __syncthreads();
    int p = blockIdx.x * 128 + threadIdx.x;
    const float* src = g_ao[a] + b * 32 * NP;
    float xn[32];
#pragma unroll
    for (int c = 0; c < 32; c++) xn[c] = fmaf(src[c * NP + p], sa_[c], sd_[c]);
    float* dst = g_up[a] + b * 64 * NP;
#pragma unroll
    for (int o = 0; o < 64; o++) {
        float acc = sb2[o];
#pragma unroll
        for (int c = 0; c < 32; c++) acc = fmaf(sw[o * 32 + c], xn[c], acc);
        dst[o * NP + p] = acc;
    }
}

// ---------------- K7: upsample + combine ----------------
__device__ __forceinline__ float tri8(const float* __restrict__ s,
                                      int p00, int p01, int p10, int p11,
                                      int w0, int w1, float ww, float wh, float wt) {
    float c00 = s[p00 + w0]; c00 += (s[p00 + w1] - c00) * ww;
    float c01 = s[p01 + w0]; c01 += (s[p01 + w1] - c01) * ww;
    float c10 = s[p10 + w0]; c10 += (s[p10 + w1] - c10) * ww;
    float c11 = s[p11 + w0]; c11 += (s[p11 + w1] - c11) * ww;
    float c0 = c00 + (c01 - c00) * wh;
    float c1 = c10 + (c11 - c10) * wh;
    return c0 + (c1 - c0) * wt;
}

__global__ void k_final(const float* __restrict__ xc, float* __restrict__ out) {
    int idx = blockIdx.x * 256 + threadIdx.x;
    int w = idx % WF;
    int h = (idx / WF) % HF;
    int t = (idx / (WF * HF)) % TF;
    int bc = idx / (WF * HF * TF);

    float pt = (float)t * (7.0f / 15.0f);
    int t0 = (int)pt; float wt = pt - (float)t0; int t1 = min(t0 + 1, 7); t0 = min(t0, 7);
    float ph = (float)h * (23.0f / 47.0f);
    int h0 = (int)ph; float wh = ph - (float)h0; int h1 = min(h0 + 1, 23); h0 = min(h0, 23);
    float pw = (float)w * (23.0f / 47.0f);
    int w0 = (int)pw; float ww = pw - (float)w0; int w1 = min(w0 + 1, 23); w0 = min(w0, 23);

    int base = bc * NP;
    int p00 = t0 * (HHd * WWd) + h0 * WWd;
    int p01 = t0 * (HHd * WWd) + h1 * WWd;
    int p10 = t1 * (HHd * WWd) + h0 * WWd;
    int p11 = t1 * (HHd * WWd) + h1 * WWd;

    float r_cross = tri8(g_up[0] + base, p00, p01, p10, p11, w0, w1, ww, wh, wt);
    float r_self  = tri8(g_up[1] + base, p00, p01, p10, p11, w0, w1, ww, wh, wt);
    out[idx] = r_self + xc[idx] - 0.5f * r_cross;
}

// ---------------- launch ----------------
extern "C" void kernel_launch(void* const* d_in, const int* in_sizes, int n_in,
                              void* d_out, int out_size) {
    const float* x       = (const float*)d_in[0];
    const float* x_c     = (const float*)d_in[1];
    const float* w_down  = (const float*)d_in[2];
    const float* b_down  = (const float*)d_in[3];
    const float* w_downc = (const float*)d_in[4];
    const float* b_downc = (const float*)d_in[5];
    const float* w_q     = (const float*)d_in[6];
    const float* b_q     = (const float*)d_in[7];
    const float* w_k     = (const float*)d_in[8];
    const float* b_k     = (const float*)d_in[9];
    const float* w_v     = (const float*)d_in[10];
    const float* b_v     = (const float*)d_in[11];
    const float* w_qsa   = (const float*)d_in[12];
    const float* b_qsa   = (const float*)d_in[13];
    const float* w_ksa   = (const float*)d_in[14];
    const float* b_ksa   = (const float*)d_in[15];
    const float* w_vsa   = (const float*)d_in[16];
    const float* b_vsa   = (const float*)d_in[17];
    const float* gn_w    = (const float*)d_in[18];
    const float* gn_b    = (const float*)d_in[19];
    const float* gn_wsa  = (const float*)d_in[20];
    const float* gn_bsa  = (const float*)d_in[21];
    const float* w_up    = (const float*)d_in[22];
    const float* b_up    = (const float*)d_in[23];
    const float* w_upsa  = (const float*)d_in[24];
    const float* b_upsa  = (const float*)d_in[25];
    const float* offset  = (const float*)d_in[26];
    const float* offsetc = (const float*)d_in[27];

    dim3 g1(2304, 1, 2);
    k_resize<<<g1, 256>>>(x, x_c);

    dim3 g2(72, 1, 2);
    k_down<<<g2, 128>>>(w_down, b_down, w_downc, b_downc);

    dim3 g3(72, 1, 2);
    k_proj<<<g3, 128>>>(w_q, b_q, w_k, b_k, w_v, b_v,
                        w_qsa, b_qsa, w_ksa, b_ksa, w_vsa, b_vsa,
                        offset, offsetc);

    dim3 g4(72, NB, 4);
    k_attn<<<g4, 128>>>();

    k_statsnorm<<<128, 256>>>();

    dim3 g6(36, NB, 2);
    k_gnup<<<g6, 128>>>(gn_w, gn_b, gn_wsa, gn_bsa, w_up, b_up, w_upsa, b_upsa);

    k_final<<<18432, 256>>>(x_c, (float*)d_out);
}

// round 14
// speedup vs baseline: 1.0710x; 1.0045x over previous
#include <cuda_runtime.h>
#include <cuda_bf16.h>
#include <cstdint>

// ---------------- constants ----------------
#define NB    2
#define CIN   64
#define CD    32
#define HHd   24
#define WWd   24
#define NP    4608          // 8*24*24
#define TF    16
#define HF    48
#define WF    48
#define NTOT  (32*NP)
#define KT    128
#define NKT   (NP/KT)       // 36
#define QSCALE 0.72134752044482f   // 0.5 * log2(e): scores land in log2 domain

typedef unsigned long long u64;

// ---------------- scratch ----------------
__device__ float g_xd [NB*CD*NP];
__device__ float g_xcd[NB*CD*NP];
// Q/K: per row 8 u64 slots, reordered: pos 2t = old slot t, pos 2t+1 = old slot t+4
__device__ __align__(16) u64 g_qhl[2*NB*NP*8];
__device__ __align__(16) u64 g_khl[2*NB*NP*8];
// V: per (ab,ch): NP/16 groups x 32B; group block: slot t(8B) = {pair(16g+2t,+1), pair(16g+2t+8,+9)}
__device__ __align__(16) char g_vp[(size_t)2*NB*32*NP*2];
__device__ float g_ao [2][NB*32*NP];
__device__ float g_up [2][NB*64*NP];
__device__ double g_psum[4][32][2];

// ---------------- helpers ----------------
__device__ __forceinline__ uint32_t smem_u32(const void* p) {
    uint32_t a;
    asm("{ .reg .u64 t; cvta.to.shared.u64 t, %1; cvt.u32.u64 %0, t; }" : "=r"(a) : "l"(p));
    return a;
}
__device__ __forceinline__ uint32_t pkb(__nv_bfloat16 lo, __nv_bfloat16 hi) {
    return ((uint32_t)__bfloat16_as_ushort(hi) << 16) | (uint32_t)__bfloat16_as_ushort(lo);
}
__device__ __forceinline__ uint32_t pkbf2(float lo, float hi) {
    uint32_t r;
    asm("cvt.rn.bf16x2.f32 %0, %1, %2;" : "=r"(r) : "f"(hi), "f"(lo));
    return r;
}
__device__ __forceinline__ float ex2f(float x) {
    float r;
    asm("ex2.approx.f32 %0, %1;" : "=f"(r) : "f"(x));
    return r;
}
__device__ __forceinline__ void mma_bf16(float* c, const uint32_t* a, uint32_t b0, uint32_t b1) {
    asm volatile(
        "mma.sync.aligned.m16n8k16.row.col.f32.bf16.bf16.f32 "
        "{%0,%1,%2,%3}, {%4,%5,%6,%7}, {%8,%9}, {%0,%1,%2,%3};"
        : "+f"(c[0]), "+f"(c[1]), "+f"(c[2]), "+f"(c[3])
        : "r"(a[0]), "r"(a[1]), "r"(a[2]), "r"(a[3]), "r"(b0), "r"(b1));
}
__device__ __forceinline__ void cpa16(uint32_t dst, const void* src) {
    asm volatile("cp.async.cg.shared.global [%0], [%1], 16;" :: "r"(dst), "l"(src) : "memory");
}
#define CP_COMMIT() asm volatile("cp.async.commit_group;" ::: "memory")
#define CP_WAIT1()  asm volatile("cp.async.wait_group 1;" ::: "memory")
#define CP_WAIT0()  asm volatile("cp.async.wait_group 0;" ::: "memory")

// ---------------- K1: fused trilinear downsample + down conv 64 -> 32 ----------------
// z = 0: x -> g_xd (w_down); z = 1: x_c -> g_xcd (w_down_c)
__global__ __launch_bounds__(128) void k_rdown(
    const float* __restrict__ x, const float* __restrict__ xc,
    const float* __restrict__ wd, const float* __restrict__ bd,
    const float* __restrict__ wdc, const float* __restrict__ bdc) {
    __shared__ float sw[CD * CIN];
    __shared__ float sb[CD];
    int z = blockIdx.z;
    const float* w  = z ? wdc : wd;
    const float* bb = z ? bdc : bd;
    const float* src = z ? xc : x;
    float* out = z ? g_xcd : g_xd;
    for (int i = threadIdx.x; i < CD * CIN; i += 128) sw[i] = w[i];
    if (threadIdx.x < CD) sb[threadIdx.x] = bb[threadIdx.x];
    __syncthreads();

    int idx = blockIdx.x * 128 + threadIdx.x;   // < NB*NP
    int b = idx / NP, p = idx % NP;
    int wq = p % WWd, h = (p / WWd) % HHd, t = p / (WWd * HHd);

    float pt = (float)t * (15.0f / 7.0f);
    int t0 = (int)pt; float wt = pt - (float)t0; int t1 = min(t0 + 1, 15); t0 = min(t0, 15);
    float ph = (float)h * (47.0f / 23.0f);
    int h0 = (int)ph; float wh = ph - (float)h0; int h1 = min(h0 + 1, 47); h0 = min(h0, 47);
    float pw = (float)wq * (47.0f / 23.0f);
    int w0 = (int)pw; float ww = pw - (float)w0; int w1 = min(w0 + 1, 47); w0 = min(w0, 47);

    const float* base = src + (size_t)b * (CIN * TF * HF * WF);
    int o00 = t0 * (HF * WF) + h0 * WF;
    int o01 = t0 * (HF * WF) + h1 * WF;
    int o10 = t1 * (HF * WF) + h0 * WF;
    int o11 = t1 * (HF * WF) + h1 * WF;

    float xin[CIN];
#pragma unroll 8
    for (int c = 0; c < CIN; c++) {
        const float* bc_ = base + (size_t)c * (TF * HF * WF);
        float c00 = __ldg(bc_ + o00 + w0); c00 += (__ldg(bc_ + o00 + w1) - c00) * ww;
        float c01 = __ldg(bc_ + o01 + w0); c01 += (__ldg(bc_ + o01 + w1) - c01) * ww;
        float c10 = __ldg(bc_ + o10 + w0); c10 += (__ldg(bc_ + o10 + w1) - c10) * ww;
        float c11 = __ldg(bc_ + o11 + w0); c11 += (__ldg(bc_ + o11 + w1) - c11) * ww;
        float c0 = c00 + (c01 - c00) * wh;
        float c1 = c10 + (c11 - c10) * wh;
        xin[c] = c0 + (c1 - c0) * wt;
    }
#pragma unroll
    for (int o = 0; o < CD; o++) {
        float acc = sb[o];
#pragma unroll
        for (int c = 0; c < CIN; c++) acc = fmaf(sw[o * CIN + c], xin[c], acc);
        out[(b * CD + o) * NP + p] = acc;
    }
}

// ---------------- K3: QKV projections + RoPE -> packed layouts ----------------
// slot i (channel pair 2i,2i+1) -> memory position ((i&3)<<1) | (i>>2)
__device__ __forceinline__ void store_hl16i(u64* d, const float* v) {
#pragma unroll
    for (int i = 0; i < 8; i++) {
        float v0 = v[2 * i], v1 = v[2 * i + 1];
        __nv_bfloat16 h0 = __float2bfloat16(v0);
        __nv_bfloat16 h1 = __float2bfloat16(v1);
        __nv_bfloat16 e0 = __float2bfloat16(v0 - __bfloat162float(h0));
        __nv_bfloat16 e1 = __float2bfloat16(v1 - __bfloat162float(h1));
        d[((i & 3) << 1) | (i >> 2)] = ((u64)pkb(e0, e1) << 32) | (u64)pkb(h0, h1);
    }
}
__device__ __forceinline__ void store_v(char* base_ab_ch, int p, float val) {
    int gi = p >> 4, r = p & 15;
    int ofs = ((r & 7) >> 1) * 8 + ((r >> 3) & 1) * 4 + (r & 1) * 2;
    *(__nv_bfloat16*)(base_ab_ch + (size_t)gi * 32 + ofs) = __float2bfloat16(val);
}

// z = 0: q,k,v (attn 0) ; z = 1: q_sa,k_sa,v_sa (attn 1)
__global__ __launch_bounds__(128) void k_proj(
    const float* __restrict__ wq,  const float* __restrict__ bq,
    const float* __restrict__ wk,  const float* __restrict__ bk,
    const float* __restrict__ wv,  const float* __restrict__ bv,
    const float* __restrict__ wqs, const float* __restrict__ bqs,
    const float* __restrict__ wks, const float* __restrict__ bks,
    const float* __restrict__ wvs, const float* __restrict__ bvs,
    const float* __restrict__ off, const float* __restrict__ offc) {
    int z = blockIdx.z;
    __shared__ float s_wq[512], s_wk[512], s_wv[1024];
    __shared__ float s_bq[16], s_bk[16], s_bv[32];
    {
        const float* WQ = z ? wqs : wq;
        const float* WK = z ? wks : wk;
        const float* WV = z ? wvs : wv;
        const float* BQ = z ? bqs : bq;
        const float* BK = z ? bks : bk;
        const float* BV = z ? bvs : bv;
        for (int i = threadIdx.x; i < 512; i += 128) { s_wq[i] = WQ[i]; s_wk[i] = WK[i]; }
        for (int i = threadIdx.x; i < 1024; i += 128) s_wv[i] = WV[i];
        if (threadIdx.x < 16) { s_bq[threadIdx.x] = BQ[threadIdx.x]; s_bk[threadIdx.x] = BK[threadIdx.x]; }
        if (threadIdx.x < 32) s_bv[threadIdx.x] = BV[threadIdx.x];
    }
    __syncthreads();

    int idx = blockIdx.x * 128 + threadIdx.x;
    int b = idx / NP, p = idx % NP, t = p / (HHd * WWd);
    int ab = z * NB + b;

    float xq[32], xcd[32];
#pragma unroll
    for (int c = 0; c < 32; c++) xcd[c] = g_xcd[(b * 32 + c) * NP + p];
    if (z == 0) {
#pragma unroll
        for (int c = 0; c < 32; c++) xq[c] = g_xd[(b * 32 + c) * NP + p];
    } else {
#pragma unroll
        for (int c = 0; c < 32; c++) xq[c] = xcd[c];
    }

    const float invf[8] = {1.0f, 0.31622776601683794f, 0.1f, 0.031622776601683794f,
                           0.01f, 0.0031622776601683794f, 0.001f, 0.00031622776601683794f};
    float se[8], ce[8], sk_[8], ck_[8];
    float tf = (float)t;
#pragma unroll
    for (int i = 0; i < 8; i++) {
        float a = tf * invf[i];
        float s = sinf(a), c = cosf(a);
        float o1 = off[i * 500 + t];
        se[i] = s + o1; ce[i] = c + o1;          // same offset on sin AND cos (per reference)
        if (z == 0) {
            float o2 = offc[i * 500 + t];
            sk_[i] = s + o2; ck_[i] = c + o2;
        } else {
            sk_[i] = se[i]; ck_[i] = ce[i];
        }
    }

    float tmp[16], rv[16];
    int row = ab * NP + p;

#pragma unroll
    for (int o = 0; o < 16; o++) {
        float acc = s_bq[o];
#pragma unroll
        for (int c = 0; c < 32; c++) acc = fmaf(s_wq[o * 32 + c], xq[c], acc);
        tmp[o] = acc;
    }
#pragma unroll
    for (int i = 0; i < 8; i++) {
        rv[i]     = QSCALE * (tmp[i] * ce[i] - tmp[8 + i] * se[i]);
        rv[8 + i] = QSCALE * (tmp[8 + i] * ce[i] + tmp[i] * se[i]);
    }
    store_hl16i(g_qhl + (size_t)row * 8, rv);

#pragma unroll
    for (int o = 0; o < 16; o++) {
        float acc = s_bk[o];
#pragma unroll
        for (int c = 0; c < 32; c++) acc = fmaf(s_wk[o * 32 + c], xcd[c], acc);
        tmp[o] = acc;
    }
#pragma unroll
    for (int i = 0; i < 8; i++) {
        rv[i]     = tmp[i] * ck_[i] - tmp[8 + i] * sk_[i];
        rv[8 + i] = tmp[8 + i] * ck_[i] + tmp[i] * sk_[i];
    }
    store_hl16i(g_khl + (size_t)row * 8, rv);

#pragma unroll
    for (int o = 0; o < 32; o++) {
        float acc = s_bv[o];
#pragma unroll
        for (int c = 0; c < 32; c++) acc = fmaf(s_wv[o * 32 + c], xcd[c], acc);
        store_v(g_vp + (size_t)(ab * 32 + o) * (NP * 2), p, acc);
    }
}

// ---------------- K4: single-pass shift-free FA mma.sync attention ----------------
__device__ __forceinline__ void stage_tile(const char* gk, const char* gv,
                                           uint32_t skb, uint32_t svb,
                                           int tid, int tile, int buf) {
    const char* ks = gk + (size_t)tile * 8192;
    uint32_t kd = skb + (uint32_t)buf * 8192;
#pragma unroll
    for (int n = 0; n < 4; n++) {
        uint32_t off = (uint32_t)(tid + n * 128) * 16;
        uint32_t key = off >> 6;
        cpa16(kd + (off ^ ((key & 3) << 5)), ks + off);
    }
    const char* vs = gv + (size_t)tile * 256;
    uint32_t vd = svb + (uint32_t)buf * 8192;
#pragma unroll
    for (int n = 0; n < 4; n++) {
        int w = tid + n * 128;
        int ch = w >> 4, wi = w & 15;
        uint32_t off = (uint32_t)(ch * 256 + wi * 16);
        cpa16(vd + (off ^ (((uint32_t)ch & 3) << 5)), vs + (size_t)ch * (NP * 2) + wi * 16);
    }
}

__global__ __launch_bounds__(128) void k_attn() {
    __shared__ __align__(128) char sKs[2][8192];
    __shared__ __align__(128) char sVs[2][8192];
    int a = blockIdx.z;
    int b = blockIdx.y;
    int ab = a * NB + b;
    int tid = threadIdx.x;
    int wid = tid >> 5, lane = tid & 31;
    int g = lane >> 2, t = lane & 3;
    int q0 = blockIdx.x * 64 + wid * 16;

    const u64* QHL = g_qhl + (size_t)ab * NP * 8;
    const char* gk = (const char*)(g_khl + (size_t)ab * NP * 8);
    const char* gv = g_vp + (size_t)ab * 32 * (NP * 2);
    float* O = g_ao[a] + b * 32 * NP;

    uint32_t skb = smem_u32(sKs);
    uint32_t svb = smem_u32(sVs);
    uint32_t swz = ((uint32_t)g & 3) << 5;

    uint32_t qh[4], ql[4];
    {
        int r0 = q0 + g, r1 = r0 + 8;
        u64 w0 = QHL[r0 * 8 + 2 * t];
        u64 w2 = QHL[r0 * 8 + 2 * t + 1];
        u64 w1 = QHL[r1 * 8 + 2 * t];
        u64 w3 = QHL[r1 * 8 + 2 * t + 1];
        qh[0] = (uint32_t)w0; ql[0] = (uint32_t)(w0 >> 32);
        qh[1] = (uint32_t)w1; ql[1] = (uint32_t)(w1 >> 32);
        qh[2] = (uint32_t)w2; ql[2] = (uint32_t)(w2 >> 32);
        qh[3] = (uint32_t)w3; ql[3] = (uint32_t)(w3 >> 32);
    }

    float oacc[16];
#pragma unroll
    for (int i = 0; i < 16; i++) oacc[i] = 0.0f;
    float ls0 = 0.0f, ls1 = 0.0f;

    stage_tile(gk, gv, skb, svb, tid, 0, 0);
    CP_COMMIT();

    for (int kk = 0; kk < NKT; kk++) {
        int buf = kk & 1;
        if (kk + 1 < NKT) {
            stage_tile(gk, gv, skb, svb, tid, kk + 1, (kk + 1) & 1);
            CP_COMMIT();
            CP_WAIT1();
        } else {
            CP_WAIT0();
        }
        __syncthreads();

        uint32_t kb = skb + (uint32_t)buf * 8192;
        uint32_t vbb = svb + (uint32_t)buf * 8192;

#pragma unroll
        for (int half = 0; half < 2; half++) {
            float acc[8][4];
#pragma unroll
            for (int j = 0; j < 8; j++) {
                acc[j][0] = acc[j][1] = acc[j][2] = acc[j][3] = 0.0f;
            }
#pragma unroll
            for (int j = 0; j < 8; j++) {
                uint32_t row = (uint32_t)(half * 64 + 8 * j + g) * 64 + (uint32_t)t * 16;
                uint32_t addr = kb + (row ^ swz);
                uint32_t b0h, b0l, b1h, b1l;
                asm("ld.shared.v4.b32 {%0,%1,%2,%3}, [%4];"
                    : "=r"(b0h), "=r"(b0l), "=r"(b1h), "=r"(b1l) : "r"(addr));
                mma_bf16(acc[j], qh, b0h, b1h);
                mma_bf16(acc[j], ql, b0h, b1h);
                mma_bf16(acc[j], qh, b0l, b1l);
            }
#pragma unroll
            for (int kc = 0; kc < 4; kc++) {
                float p0 = ex2f(acc[2 * kc][0]);
                float p1 = ex2f(acc[2 * kc][1]);
                float p2 = ex2f(acc[2 * kc][2]);
                float p3 = ex2f(acc[2 * kc][3]);
                float p4 = ex2f(acc[2 * kc + 1][0]);
                float p5 = ex2f(acc[2 * kc + 1][1]);
                float p6 = ex2f(acc[2 * kc + 1][2]);
                float p7 = ex2f(acc[2 * kc + 1][3]);
                ls0 += (p0 + p1) + (p4 + p5);
                ls1 += (p2 + p3) + (p6 + p7);
                uint32_t pa[4] = { pkbf2(p0, p1), pkbf2(p2, p3), pkbf2(p4, p5), pkbf2(p6, p7) };
#pragma unroll
                for (int j2 = 0; j2 < 4; j2++) {
                    uint32_t off = (uint32_t)((8 * j2 + g) * 256 + (half * 4 + kc) * 32 + t * 8);
                    uint32_t addr = vbb + (off ^ swz);
                    uint32_t vb0, vb1;
                    asm("ld.shared.v2.b32 {%0,%1}, [%2];" : "=r"(vb0), "=r"(vb1) : "r"(addr));
                    mma_bf16(&oacc[4 * j2], pa, vb0, vb1);
                }
            }
        }
        __syncthreads();
    }

    float l0 = ls0;
    l0 += __shfl_xor_sync(0xffffffffu, l0, 1);
    l0 += __shfl_xor_sync(0xffffffffu, l0, 2);
    float l1 = ls1;
    l1 += __shfl_xor_sync(0xffffffffu, l1, 1);
    l1 += __shfl_xor_sync(0xffffffffu, l1, 2);
    float inv0 = 1.0f / l0, inv1 = 1.0f / l1;

    int r0 = q0 + g, r1 = r0 + 8;
#pragma unroll
    for (int j2 = 0; j2 < 4; j2++) {
        int ch = 8 * j2 + 2 * t;
        O[ch * NP + r0]       = oacc[4 * j2 + 0] * inv0;
        O[(ch + 1) * NP + r0] = oacc[4 * j2 + 1] * inv0;
        O[ch * NP + r1]       = oacc[4 * j2 + 2] * inv1;
        O[(ch + 1) * NP + r1] = oacc[4 * j2 + 3] * inv1;
    }
}

// ---------------- K5: GN partial stats (128 blocks, one per (ab, channel)) ----------------
__global__ __launch_bounds__(256) void k_stats() {
    int gb = blockIdx.x >> 5;            // ab
    int c  = blockIdx.x & 31;            // channel
    const float* src = g_ao[gb >> 1] + (gb & 1) * 32 * NP + c * NP;

    float s1 = 0.0f;
    double s2 = 0.0;
    for (int i = threadIdx.x; i < NP; i += 256) {
        float v = src[i];
        s1 += v;
        s2 += (double)v * (double)v;
    }
    __shared__ float  r1[256];
    __shared__ double r2[256];
    r1[threadIdx.x] = s1; r2[threadIdx.x] = s2;
    __syncthreads();
    for (int s = 128; s > 0; s >>= 1) {
        if (threadIdx.x < s) { r1[threadIdx.x] += r1[threadIdx.x + s]; r2[threadIdx.x] += r2[threadIdx.x + s]; }
        __syncthreads();
    }
    if (threadIdx.x == 0) {
        g_psum[gb][c][0] = (double)r1[0];
        g_psum[gb][c][1] = r2[0];
    }
}

// ---------------- K6: groupnorm apply + up conv 32 -> 64 ----------------
__global__ __launch_bounds__(128) void k_gnup(
    const float* __restrict__ gnw,  const float* __restrict__ gnb,
    const float* __restrict__ gnws, const float* __restrict__ gnbs,
    const float* __restrict__ wup,  const float* __restrict__ bup,
    const float* __restrict__ wups, const float* __restrict__ bups) {
    int a = blockIdx.z, b = blockIdx.y;
    int gb = a * 2 + b;
    __shared__ float sw[64 * 32];
    __shared__ float sb2[64], sa_[32], sd_[32];
    const float* w   = a ? wups : wup;
    const float* bb  = a ? bups : bup;
    const float* gw  = a ? gnws : gnw;
    const float* gbb = a ? gnbs : gnb;
    double s1 = 0.0, s2 = 0.0;
#pragma unroll
    for (int c = 0; c < 32; c++) { s1 += g_psum[gb][c][0]; s2 += g_psum[gb][c][1]; }
    double mu_d  = s1 / (double)NTOT;
    double var_d = s2 / (double)NTOT - mu_d * mu_d;
    float mu = (float)mu_d;
    float rstd = rsqrtf((float)var_d + 1e-5f);
    for (int i = threadIdx.x; i < 2048; i += 128) sw[i] = w[i];
    if (threadIdx.x < 64) sb2[threadIdx.x] = bb[threadIdx.x];
    if (threadIdx.x < 32) {
        float aa = rstd * gw[threadIdx.x];
        sa_[threadIdx.x] = aa;
        sd_[threadIdx.x] = gbb[threadIdx.x] - mu * aa;
    }
    __syncthreads();
    int p = blockIdx.x * 128 + threadIdx.x;
    const float* src = g_ao[a] + b * 32 * NP;
    float xn[32];
#pragma unroll
    for (int c = 0; c < 32; c++) xn[c] = fmaf(src[c * NP + p], sa_[c], sd_[c]);
    float* dst = g_up[a] + b * 64 * NP;
#pragma unroll
    for (int o = 0; o < 64; o++) {
        float acc = sb2[o];
#pragma unroll
        for (int c = 0; c < 32; c++) acc = fmaf(sw[o * 32 + c], xn[c], acc);
        dst[o * NP + p] = acc;
    }
}

// ---------------- K7: upsample + combine ----------------
__device__ __forceinline__ float tri8(const float* __restrict__ s,
                                      int p00, int p01, int p10, int p11,
                                      int w0, int w1, float ww, float wh, float wt) {
    float c00 = s[p00 + w0]; c00 += (s[p00 + w1] - c00) * ww;
    float c01 = s[p01 + w0]; c01 += (s[p01 + w1] - c01) * ww;
    float c10 = s[p10 + w0]; c10 += (s[p10 + w1] - c10) * ww;
    float c11 = s[p11 + w0]; c11 += (s[p11 + w1] - c11) * ww;
    float c0 = c00 + (c01 - c00) * wh;
    float c1 = c10 + (c11 - c10) * wh;
    return c0 + (c1 - c0) * wt;
}

__global__ void k_final(const float* __restrict__ xc, float* __restrict__ out) {
    int idx = blockIdx.x * 256 + threadIdx.x;
    int w = idx % WF;
    int h = (idx / WF) % HF;
    int t = (idx / (WF * HF)) % TF;
    int bc = idx / (WF * HF * TF);

    float pt = (float)t * (7.0f / 15.0f);
    int t0 = (int)pt; float wt = pt - (float)t0; int t1 = min(t0 + 1, 7); t0 = min(t0, 7);
    float ph = (float)h * (23.0f / 47.0f);
    int h0 = (int)ph; float wh = ph - (float)h0; int h1 = min(h0 + 1, 23); h0 = min(h0, 23);
    float pw = (float)w * (23.0f / 47.0f);
    int w0 = (int)pw; float ww = pw - (float)w0; int w1 = min(w0 + 1, 23); w0 = min(w0, 23);

    int base = bc * NP;
    int p00 = t0 * (HHd * WWd) + h0 * WWd;
    int p01 = t0 * (HHd * WWd) + h1 * WWd;
    int p10 = t1 * (HHd * WWd) + h0 * WWd;
    int p11 = t1 * (HHd * WWd) + h1 * WWd;

    float r_cross = tri8(g_up[0] + base, p00, p01, p10, p11, w0, w1, ww, wh, wt);
    float r_self  = tri8(g_up[1] + base, p00, p01, p10, p11, w0, w1, ww, wh, wt);
    out[idx] = r_self + xc[idx] - 0.5f * r_cross;
}

// ---------------- launch ----------------
extern "C" void kernel_launch(void* const* d_in, const int* in_sizes, int n_in,
                              void* d_out, int out_size) {
    const float* x       = (const float*)d_in[0];
    const float* x_c     = (const float*)d_in[1];
    const float* w_down  = (const float*)d_in[2];
    const float* b_down  = (const float*)d_in[3];
    const float* w_downc = (const float*)d_in[4];
    const float* b_downc = (const float*)d_in[5];
    const float* w_q     = (const float*)d_in[6];
    const float* b_q     = (const float*)d_in[7];
    const float* w_k     = (const float*)d_in[8];
    const float* b_k     = (const float*)d_in[9];
    const float* w_v     = (const float*)d_in[10];
    const float* b_v     = (const float*)d_in[11];
    const float* w_qsa   = (const float*)d_in[12];
    const float* b_qsa   = (const float*)d_in[13];
    const float* w_ksa   = (const float*)d_in[14];
    const float* b_ksa   = (const float*)d_in[15];
    const float* w_vsa   = (const float*)d_in[16];
    const float* b_vsa   = (const float*)d_in[17];
    const float* gn_w    = (const float*)d_in[18];
    const float* gn_b    = (const float*)d_in[19];
    const float* gn_wsa  = (const float*)d_in[20];
    const float* gn_bsa  = (const float*)d_in[21];
    const float* w_up    = (const float*)d_in[22];
    const float* b_up    = (const float*)d_in[23];
    const float* w_upsa  = (const float*)d_in[24];
    const float* b_upsa  = (const float*)d_in[25];
    const float* offset  = (const float*)d_in[26];
    const float* offsetc = (const float*)d_in[27];

    dim3 g2(72, 1, 2);
    k_rdown<<<g2, 128>>>(x, x_c, w_down, b_down, w_downc, b_downc);

    dim3 g3(72, 1, 2);
    k_proj<<<g3, 128>>>(w_q, b_q, w_k, b_k, w_v, b_v,
                        w_qsa, b_qsa, w_ksa, b_ksa, w_vsa, b_vsa,
                        offset, offsetc);

    dim3 g4(72, NB, 2);
    k_attn<<<g4, 128>>>();

    k_stats<<<128, 256>>>();

    dim3 g6(36, NB, 2);
    k_gnup<<<g6, 128>>>(gn_w, gn_b, gn_wsa, gn_bsa, w_up, b_up, w_upsa, b_upsa);

    k_final<<<18432, 256>>>(x_c, (float*)d_out);
}

// round 16
// speedup vs baseline: 1.1116x; 1.0379x over previous
#include <cuda_runtime.h>
#include <cuda_bf16.h>
#include <cstdint>

// ---------------- constants ----------------
#define NB    2
#define CIN   64
#define CD    32
#define HHd   24
#define WWd   24
#define NP    4608          // 8*24*24
#define TF    16
#define HF    48
#define WF    48
#define NTOT  (32*NP)
#define KT    128
#define NKT   (NP/KT)       // 36
#define QSCALE 0.72134752044482f   // 0.5 * log2(e): scores land in log2 domain

typedef unsigned long long u64;

// ---------------- scratch ----------------
__device__ float g_xd [NB*CD*NP];
__device__ float g_xcd[NB*CD*NP];
// Q/K: per row 8 u64 slots, reordered: pos 2t = old slot t, pos 2t+1 = old slot t+4
__device__ __align__(16) u64 g_qhl[2*NB*NP*8];
__device__ __align__(16) u64 g_khl[2*NB*NP*8];
// V: per (ab,ch): NP/16 groups x 32B; group block: slot t(8B) = {pair(16g+2t,+1), pair(16g+2t+8,+9)}
__device__ __align__(16) char g_vp[(size_t)2*NB*32*NP*2];
__device__ float g_ao [2][NB*32*NP];
__device__ float g_up [2][NB*64*NP];
__device__ double g_psum[4][32][2];

// ---------------- helpers ----------------
__device__ __forceinline__ uint32_t smem_u32(const void* p) {
    uint32_t a;
    asm("{ .reg .u64 t; cvta.to.shared.u64 t, %1; cvt.u32.u64 %0, t; }" : "=r"(a) : "l"(p));
    return a;
}
__device__ __forceinline__ uint32_t pkb(__nv_bfloat16 lo, __nv_bfloat16 hi) {
    return ((uint32_t)__bfloat16_as_ushort(hi) << 16) | (uint32_t)__bfloat16_as_ushort(lo);
}
__device__ __forceinline__ uint32_t pkbf2(float lo, float hi) {
    uint32_t r;
    asm("cvt.rn.bf16x2.f32 %0, %1, %2;" : "=r"(r) : "f"(hi), "f"(lo));
    return r;
}
__device__ __forceinline__ float ex2f(float x) {
    float r;
    asm("ex2.approx.f32 %0, %1;" : "=f"(r) : "f"(x));
    return r;
}
__device__ __forceinline__ void mma_bf16(float* c, const uint32_t* a, uint32_t b0, uint32_t b1) {
    asm volatile(
        "mma.sync.aligned.m16n8k16.row.col.f32.bf16.bf16.f32 "
        "{%0,%1,%2,%3}, {%4,%5,%6,%7}, {%8,%9}, {%0,%1,%2,%3};"
        : "+f"(c[0]), "+f"(c[1]), "+f"(c[2]), "+f"(c[3])
        : "r"(a[0]), "r"(a[1]), "r"(a[2]), "r"(a[3]), "r"(b0), "r"(b1));
}
__device__ __forceinline__ void cpa16(uint32_t dst, const void* src) {
    asm volatile("cp.async.cg.shared.global [%0], [%1], 16;" :: "r"(dst), "l"(src) : "memory");
}
#define CP_COMMIT() asm volatile("cp.async.commit_group;" ::: "memory")
#define CP_WAIT1()  asm volatile("cp.async.wait_group 1;" ::: "memory")
#define CP_WAIT0()  asm volatile("cp.async.wait_group 0;" ::: "memory")

// ---------------- K1: fused trilinear downsample + down conv 64 -> 32 ----------------
// z = 0: x -> g_xd (w_down); z = 1: x_c -> g_xcd (w_down_c)
__global__ __launch_bounds__(128) void k_rdown(
    const float* __restrict__ x, const float* __restrict__ xc,
    const float* __restrict__ wd, const float* __restrict__ bd,
    const float* __restrict__ wdc, const float* __restrict__ bdc) {
    __shared__ float sw[CD * CIN];
    __shared__ float sb[CD];
    int z = blockIdx.z;
    const float* w  = z ? wdc : wd;
    const float* bb = z ? bdc : bd;
    const float* src = z ? xc : x;
    float* out = z ? g_xcd : g_xd;
    for (int i = threadIdx.x; i < CD * CIN; i += 128) sw[i] = w[i];
    if (threadIdx.x < CD) sb[threadIdx.x] = bb[threadIdx.x];
    __syncthreads();

    int idx = blockIdx.x * 128 + threadIdx.x;   // < NB*NP
    int b = idx / NP, p = idx % NP;
    int wq = p % WWd, h = (p / WWd) % HHd, t = p / (WWd * HHd);

    float pt = (float)t * (15.0f / 7.0f);
    int t0 = (int)pt; float wt = pt - (float)t0; int t1 = min(t0 + 1, 15); t0 = min(t0, 15);
    float ph = (float)h * (47.0f / 23.0f);
    int h0 = (int)ph; float wh = ph - (float)h0; int h1 = min(h0 + 1, 47); h0 = min(h0, 47);
    float pw = (float)wq * (47.0f / 23.0f);
    int w0 = (int)pw; float ww = pw - (float)w0; int w1 = min(w0 + 1, 47); w0 = min(w0, 47);

    const float* base = src + (size_t)b * (CIN * TF * HF * WF);
    int o00 = t0 * (HF * WF) + h0 * WF;
    int o01 = t0 * (HF * WF) + h1 * WF;
    int o10 = t1 * (HF * WF) + h0 * WF;
    int o11 = t1 * (HF * WF) + h1 * WF;

    float xin[CIN];
#pragma unroll 8
    for (int c = 0; c < CIN; c++) {
        const float* bc_ = base + (size_t)c * (TF * HF * WF);
        float c00 = __ldg(bc_ + o00 + w0); c00 += (__ldg(bc_ + o00 + w1) - c00) * ww;
        float c01 = __ldg(bc_ + o01 + w0); c01 += (__ldg(bc_ + o01 + w1) - c01) * ww;
        float c10 = __ldg(bc_ + o10 + w0); c10 += (__ldg(bc_ + o10 + w1) - c10) * ww;
        float c11 = __ldg(bc_ + o11 + w0); c11 += (__ldg(bc_ + o11 + w1) - c11) * ww;
        float c0 = c00 + (c01 - c00) * wh;
        float c1 = c10 + (c11 - c10) * wh;
        xin[c] = c0 + (c1 - c0) * wt;
    }
#pragma unroll
    for (int o = 0; o < CD; o++) {
        float acc = sb[o];
#pragma unroll
        for (int c = 0; c < CIN; c++) acc = fmaf(sw[o * CIN + c], xin[c], acc);
        out[(b * CD + o) * NP + p] = acc;
    }
}

// ---------------- K3: QKV projections + RoPE -> packed layouts ----------------
// slot i (channel pair 2i,2i+1) -> memory position ((i&3)<<1) | (i>>2)
__device__ __forceinline__ void store_hl16i(u64* d, const float* v) {
#pragma unroll
    for (int i = 0; i < 8; i++) {
        float v0 = v[2 * i], v1 = v[2 * i + 1];
        __nv_bfloat16 h0 = __float2bfloat16(v0);
        __nv_bfloat16 h1 = __float2bfloat16(v1);
        __nv_bfloat16 e0 = __float2bfloat16(v0 - __bfloat162float(h0));
        __nv_bfloat16 e1 = __float2bfloat16(v1 - __bfloat162float(h1));
        d[((i & 3) << 1) | (i >> 2)] = ((u64)pkb(e0, e1) << 32) | (u64)pkb(h0, h1);
    }
}
__device__ __forceinline__ void store_v(char* base_ab_ch, int p, float val) {
    int gi = p >> 4, r = p & 15;
    int ofs = ((r & 7) >> 1) * 8 + ((r >> 3) & 1) * 4 + (r & 1) * 2;
    *(__nv_bfloat16*)(base_ab_ch + (size_t)gi * 32 + ofs) = __float2bfloat16(val);
}

// z = 0: q,k,v (attn 0) ; z = 1: q_sa,k_sa,v_sa (attn 1)
__global__ __launch_bounds__(128) void k_proj(
    const float* __restrict__ wq,  const float* __restrict__ bq,
    const float* __restrict__ wk,  const float* __restrict__ bk,
    const float* __restrict__ wv,  const float* __restrict__ bv,
    const float* __restrict__ wqs, const float* __restrict__ bqs,
    const float* __restrict__ wks, const float* __restrict__ bks,
    const float* __restrict__ wvs, const float* __restrict__ bvs,
    const float* __restrict__ off, const float* __restrict__ offc) {
    int z = blockIdx.z;
    __shared__ float s_wq[512], s_wk[512], s_wv[1024];
    __shared__ float s_bq[16], s_bk[16], s_bv[32];
    {
        const float* WQ = z ? wqs : wq;
        const float* WK = z ? wks : wk;
        const float* WV = z ? wvs : wv;
        const float* BQ = z ? bqs : bq;
        const float* BK = z ? bks : bk;
        const float* BV = z ? bvs : bv;
        for (int i = threadIdx.x; i < 512; i += 128) { s_wq[i] = WQ[i]; s_wk[i] = WK[i]; }
        for (int i = threadIdx.x; i < 1024; i += 128) s_wv[i] = WV[i];
        if (threadIdx.x < 16) { s_bq[threadIdx.x] = BQ[threadIdx.x]; s_bk[threadIdx.x] = BK[threadIdx.x]; }
        if (threadIdx.x < 32) s_bv[threadIdx.x] = BV[threadIdx.x];
    }
    __syncthreads();

    int idx = blockIdx.x * 128 + threadIdx.x;
    int b = idx / NP, p = idx % NP, t = p / (HHd * WWd);
    int ab = z * NB + b;

    float xq[32], xcd[32];
#pragma unroll
    for (int c = 0; c < 32; c++) xcd[c] = g_xcd[(b * 32 + c) * NP + p];
    if (z == 0) {
#pragma unroll
        for (int c = 0; c < 32; c++) xq[c] = g_xd[(b * 32 + c) * NP + p];
    } else {
#pragma unroll
        for (int c = 0; c < 32; c++) xq[c] = xcd[c];
    }

    const float invf[8] = {1.0f, 0.31622776601683794f, 0.1f, 0.031622776601683794f,
                           0.01f, 0.0031622776601683794f, 0.001f, 0.00031622776601683794f};
    float se[8], ce[8], sk_[8], ck_[8];
    float tf = (float)t;
#pragma unroll
    for (int i = 0; i < 8; i++) {
        float a = tf * invf[i];
        float s = sinf(a), c = cosf(a);
        float o1 = off[i * 500 + t];
        se[i] = s + o1; ce[i] = c + o1;          // same offset on sin AND cos (per reference)
        if (z == 0) {
            float o2 = offc[i * 500 + t];
            sk_[i] = s + o2; ck_[i] = c + o2;
        } else {
            sk_[i] = se[i]; ck_[i] = ce[i];
        }
    }

    float tmp[16], rv[16];
    int row = ab * NP + p;

#pragma unroll
    for (int o = 0; o < 16; o++) {
        float acc = s_bq[o];
#pragma unroll
        for (int c = 0; c < 32; c++) acc = fmaf(s_wq[o * 32 + c], xq[c], acc);
        tmp[o] = acc;
    }
#pragma unroll
    for (int i = 0; i < 8; i++) {
        rv[i]     = QSCALE * (tmp[i] * ce[i] - tmp[8 + i] * se[i]);
        rv[8 + i] = QSCALE * (tmp[8 + i] * ce[i] + tmp[i] * se[i]);
    }
    store_hl16i(g_qhl + (size_t)row * 8, rv);

#pragma unroll
    for (int o = 0; o < 16; o++) {
        float acc = s_bk[o];
#pragma unroll
        for (int c = 0; c < 32; c++) acc = fmaf(s_wk[o * 32 + c], xcd[c], acc);
        tmp[o] = acc;
    }
#pragma unroll
    for (int i = 0; i < 8; i++) {
        rv[i]     = tmp[i] * ck_[i] - tmp[8 + i] * sk_[i];
        rv[8 + i] = tmp[8 + i] * ck_[i] + tmp[i] * sk_[i];
    }
    store_hl16i(g_khl + (size_t)row * 8, rv);

#pragma unroll
    for (int o = 0; o < 32; o++) {
        float acc = s_bv[o];
#pragma unroll
        for (int c = 0; c < 32; c++) acc = fmaf(s_wv[o * 32 + c], xcd[c], acc);
        store_v(g_vp + (size_t)(ab * 32 + o) * (NP * 2), p, acc);
    }
}

// ---------------- K4: single-pass shift-free FA mma.sync attention ----------------
__device__ __forceinline__ void stage_tile(const char* gk, const char* gv,
                                           uint32_t skb, uint32_t svb,
                                           int tid, int tile, int buf) {
    const char* ks = gk + (size_t)tile * 8192;
    uint32_t kd = skb + (uint32_t)buf * 8192;
#pragma unroll
    for (int n = 0; n < 4; n++) {
        uint32_t off = (uint32_t)(tid + n * 128) * 16;
        uint32_t key = off >> 6;
        cpa16(kd + (off ^ ((key & 3) << 5)), ks + off);
    }
    const char* vs = gv + (size_t)tile * 256;
    uint32_t vd = svb + (uint32_t)buf * 8192;
#pragma unroll
    for (int n = 0; n < 4; n++) {
        int w = tid + n * 128;
        int ch = w >> 4, wi = w & 15;
        uint32_t off = (uint32_t)(ch * 256 + wi * 16);
        cpa16(vd + (off ^ (((uint32_t)ch & 3) << 5)), vs + (size_t)ch * (NP * 2) + wi * 16);
    }
}

__global__ __launch_bounds__(128) void k_attn() {
    __shared__ __align__(128) char sKs[2][8192];
    __shared__ __align__(128) char sVs[2][8192];
    int a = blockIdx.z;
    int b = blockIdx.y;
    int ab = a * NB + b;
    int tid = threadIdx.x;
    int wid = tid >> 5, lane = tid & 31;
    int g = lane >> 2, t = lane & 3;
    int q0 = blockIdx.x * 64 + wid * 16;

    const u64* QHL = g_qhl + (size_t)ab * NP * 8;
    const char* gk = (const char*)(g_khl + (size_t)ab * NP * 8);
    const char* gv = g_vp + (size_t)ab * 32 * (NP * 2);
    float* O = g_ao[a] + b * 32 * NP;

    uint32_t skb = smem_u32(sKs);
    uint32_t svb = smem_u32(sVs);
    uint32_t swz = ((uint32_t)g & 3) << 5;

    uint32_t qh[4], ql[4];
    {
        int r0 = q0 + g, r1 = r0 + 8;
        u64 w0 = QHL[r0 * 8 + 2 * t];
        u64 w2 = QHL[r0 * 8 + 2 * t + 1];
        u64 w1 = QHL[r1 * 8 + 2 * t];
        u64 w3 = QHL[r1 * 8 + 2 * t + 1];
        qh[0] = (uint32_t)w0; ql[0] = (uint32_t)(w0 >> 32);
        qh[1] = (uint32_t)w1; ql[1] = (uint32_t)(w1 >> 32);
        qh[2] = (uint32_t)w2; ql[2] = (uint32_t)(w2 >> 32);
        qh[3] = (uint32_t)w3; ql[3] = (uint32_t)(w3 >> 32);
    }

    float oacc[16];
#pragma unroll
    for (int i = 0; i < 16; i++) oacc[i] = 0.0f;
    float ls0 = 0.0f, ls1 = 0.0f;

    stage_tile(gk, gv, skb, svb, tid, 0, 0);
    CP_COMMIT();

    for (int kk = 0; kk < NKT; kk++) {
        int buf = kk & 1;
        if (kk + 1 < NKT) {
            stage_tile(gk, gv, skb, svb, tid, kk + 1, (kk + 1) & 1);
            CP_COMMIT();
            CP_WAIT1();
        } else {
            CP_WAIT0();
        }
        __syncthreads();

        uint32_t kb = skb + (uint32_t)buf * 8192;
        uint32_t vbb = svb + (uint32_t)buf * 8192;

#pragma unroll
        for (int half = 0; half < 2; half++) {
            float acc[8][4];
#pragma unroll
            for (int j = 0; j < 8; j++) {
                acc[j][0] = acc[j][1] = acc[j][2] = acc[j][3] = 0.0f;
            }
#pragma unroll
            for (int j = 0; j < 8; j++) {
                uint32_t row = (uint32_t)(half * 64 + 8 * j + g) * 64 + (uint32_t)t * 16;
                uint32_t addr = kb + (row ^ swz);
                uint32_t b0h, b0l, b1h, b1l;
                asm("ld.shared.v4.b32 {%0,%1,%2,%3}, [%4];"
                    : "=r"(b0h), "=r"(b0l), "=r"(b1h), "=r"(b1l) : "r"(addr));
                mma_bf16(acc[j], qh, b0h, b1h);
                mma_bf16(acc[j], ql, b0h, b1h);
                mma_bf16(acc[j], qh, b0l, b1l);
            }
#pragma unroll
            for (int kc = 0; kc < 4; kc++) {
                float p0 = ex2f(acc[2 * kc][0]);
                float p1 = ex2f(acc[2 * kc][1]);
                float p2 = ex2f(acc[2 * kc][2]);
                float p3 = ex2f(acc[2 * kc][3]);
                float p4 = ex2f(acc[2 * kc + 1][0]);
                float p5 = ex2f(acc[2 * kc + 1][1]);
                float p6 = ex2f(acc[2 * kc + 1][2]);
                float p7 = ex2f(acc[2 * kc + 1][3]);
                ls0 += (p0 + p1) + (p4 + p5);
                ls1 += (p2 + p3) + (p6 + p7);
                uint32_t pa[4] = { pkbf2(p0, p1), pkbf2(p2, p3), pkbf2(p4, p5), pkbf2(p6, p7) };
#pragma unroll
                for (int j2 = 0; j2 < 4; j2++) {
                    uint32_t off = (uint32_t)((8 * j2 + g) * 256 + (half * 4 + kc) * 32 + t * 8);
                    uint32_t addr = vbb + (off ^ swz);
                    uint32_t vb0, vb1;
                    asm("ld.shared.v2.b32 {%0,%1}, [%2];" : "=r"(vb0), "=r"(vb1) : "r"(addr));
                    mma_bf16(&oacc[4 * j2], pa, vb0, vb1);
                }
            }
        }
        __syncthreads();
    }

    float l0 = ls0;
    l0 += __shfl_xor_sync(0xffffffffu, l0, 1);
    l0 += __shfl_xor_sync(0xffffffffu, l0, 2);
    float l1 = ls1;
    l1 += __shfl_xor_sync(0xffffffffu, l1, 1);
    l1 += __shfl_xor_sync(0xffffffffu, l1, 2);
    float inv0 = 1.0f / l0, inv1 = 1.0f / l1;

    int r0 = q0 + g, r1 = r0 + 8;
#pragma unroll
    for (int j2 = 0; j2 < 4; j2++) {
        int ch = 8 * j2 + 2 * t;
        O[ch * NP + r0]       = oacc[4 * j2 + 0] * inv0;
        O[(ch + 1) * NP + r0] = oacc[4 * j2 + 1] * inv0;
        O[ch * NP + r1]       = oacc[4 * j2 + 2] * inv1;
        O[(ch + 1) * NP + r1] = oacc[4 * j2 + 3] * inv1;
    }
}

// ---------------- K5: GN partial stats (fp32 chains; 128 blocks x 512 thr) ----------------
__global__ __launch_bounds__(512) void k_stats() {
    int gb = blockIdx.x >> 5;            // ab
    int c  = blockIdx.x & 31;            // channel
    const float* src = g_ao[gb >> 1] + (gb & 1) * 32 * NP + c * NP;

    float s1 = 0.0f, s2 = 0.0f;
#pragma unroll
    for (int n = 0; n < NP / 512; n++) {
        float v = src[threadIdx.x + n * 512];
        s1 += v;
        s2 = fmaf(v, v, s2);
    }
    __shared__ float r1[512];
    __shared__ float r2[512];
    r1[threadIdx.x] = s1; r2[threadIdx.x] = s2;
    __syncthreads();
    for (int s = 256; s > 0; s >>= 1) {
        if (threadIdx.x < s) { r1[threadIdx.x] += r1[threadIdx.x + s]; r2[threadIdx.x] += r2[threadIdx.x + s]; }
        __syncthreads();
    }
    if (threadIdx.x == 0) {
        g_psum[gb][c][0] = (double)r1[0];
        g_psum[gb][c][1] = (double)r2[0];
    }
}

// ---------------- K6: groupnorm apply + up conv 32 -> 64 ----------------
__global__ __launch_bounds__(128) void k_gnup(
    const float* __restrict__ gnw,  const float* __restrict__ gnb,
    const float* __restrict__ gnws, const float* __restrict__ gnbs,
    const float* __restrict__ wup,  const float* __restrict__ bup,
    const float* __restrict__ wups, const float* __restrict__ bups) {
    int a = blockIdx.z, b = blockIdx.y;
    int gb = a * 2 + b;
    __shared__ float sw[64 * 32];
    __shared__ float sb2[64], sa_[32], sd_[32];
    const float* w   = a ? wups : wup;
    const float* bb  = a ? bups : bup;
    const float* gw  = a ? gnws : gnw;
    const float* gbb = a ? gnbs : gnb;
    double s1 = 0.0, s2 = 0.0;
#pragma unroll
    for (int c = 0; c < 32; c++) { s1 += g_psum[gb][c][0]; s2 += g_psum[gb][c][1]; }
    double mu_d  = s1 / (double)NTOT;
    double var_d = s2 / (double)NTOT - mu_d * mu_d;
    float mu = (float)mu_d;
    float rstd = rsqrtf((float)var_d + 1e-5f);
    for (int i = threadIdx.x; i < 2048; i += 128) sw[i] = w[i];
    if (threadIdx.x < 64) sb2[threadIdx.x] = bb[threadIdx.x];
    if (threadIdx.x < 32) {
        float aa = rstd * gw[threadIdx.x];
        sa_[threadIdx.x] = aa;
        sd_[threadIdx.x] = gbb[threadIdx.x] - mu * aa;
    }
    __syncthreads();
    int p = blockIdx.x * 128 + threadIdx.x;
    const float* src = g_ao[a] + b * 32 * NP;
    float xn[32];
#pragma unroll
    for (int c = 0; c < 32; c++) xn[c] = fmaf(src[c * NP + p], sa_[c], sd_[c]);
    float* dst = g_up[a] + b * 64 * NP;
#pragma unroll
    for (int o = 0; o < 64; o++) {
        float acc = sb2[o];
#pragma unroll
        for (int c = 0; c < 32; c++) acc = fmaf(sw[o * 32 + c], xn[c], acc);
        dst[o * NP + p] = acc;
    }
}

// ---------------- K7: upsample + combine ----------------
__device__ __forceinline__ float tri8(const float* __restrict__ s,
                                      int p00, int p01, int p10, int p11,
                                      int w0, int w1, float ww, float wh, float wt) {
    float c00 = s[p00 + w0]; c00 += (s[p00 + w1] - c00) * ww;
    float c01 = s[p01 + w0]; c01 += (s[p01 + w1] - c01) * ww;
    float c10 = s[p10 + w0]; c10 += (s[p10 + w1] - c10) * ww;
    float c11 = s[p11 + w0]; c11 += (s[p11 + w1] - c11) * ww;
    float c0 = c00 + (c01 - c00) * wh;
    float c1 = c10 + (c11 - c10) * wh;
    return c0 + (c1 - c0) * wt;
}

__global__ void k_final(const float* __restrict__ xc, float* __restrict__ out) {
    int idx = blockIdx.x * 256 + threadIdx.x;
    int w = idx % WF;
    int h = (idx / WF) % HF;
    int t = (idx / (WF * HF)) % TF;
    int bc = idx / (WF * HF * TF);

    float pt = (float)t * (7.0f / 15.0f);
    int t0 = (int)pt; float wt = pt - (float)t0; int t1 = min(t0 + 1, 7); t0 = min(t0, 7);
    float ph = (float)h * (23.0f / 47.0f);
    int h0 = (int)ph; float wh = ph - (float)h0; int h1 = min(h0 + 1, 23); h0 = min(h0, 23);
    float pw = (float)w * (23.0f / 47.0f);
    int w0 = (int)pw; float ww = pw - (float)w0; int w1 = min(w0 + 1, 23); w0 = min(w0, 23);

    int base = bc * NP;
    int p00 = t0 * (HHd * WWd) + h0 * WWd;
    int p01 = t0 * (HHd * WWd) + h1 * WWd;
    int p10 = t1 * (HHd * WWd) + h0 * WWd;
    int p11 = t1 * (HHd * WWd) + h1 * WWd;

    float r_cross = tri8(g_up[0] + base, p00, p01, p10, p11, w0, w1, ww, wh, wt);
    float r_self  = tri8(g_up[1] + base, p00, p01, p10, p11, w0, w1, ww, wh, wt);
    out[idx] = r_self + xc[idx] - 0.5f * r_cross;
}

// ---------------- launch ----------------
extern "C" void kernel_launch(void* const* d_in, const int* in_sizes, int n_in,
                              void* d_out, int out_size) {
    const float* x       = (const float*)d_in[0];
    const float* x_c     = (const float*)d_in[1];
    const float* w_down  = (const float*)d_in[2];
    const float* b_down  = (const float*)d_in[3];
    const float* w_downc = (const float*)d_in[4];
    const float* b_downc = (const float*)d_in[5];
    const float* w_q     = (const float*)d_in[6];
    const float* b_q     = (const float*)d_in[7];
    const float* w_k     = (const float*)d_in[8];
    const float* b_k     = (const float*)d_in[9];
    const float* w_v     = (const float*)d_in[10];
    const float* b_v     = (const float*)d_in[11];
    const float* w_qsa   = (const float*)d_in[12];
    const float* b_qsa   = (const float*)d_in[13];
    const float* w_ksa   = (const float*)d_in[14];
    const float* b_ksa   = (const float*)d_in[15];
    const float* w_vsa   = (const float*)d_in[16];
    const float* b_vsa   = (const float*)d_in[17];
    const float* gn_w    = (const float*)d_in[18];
    const float* gn_b    = (const float*)d_in[19];
    const float* gn_wsa  = (const float*)d_in[20];
    const float* gn_bsa  = (const float*)d_in[21];
    const float* w_up    = (const float*)d_in[22];
    const float* b_up    = (const float*)d_in[23];
    const float* w_upsa  = (const float*)d_in[24];
    const float* b_upsa  = (const float*)d_in[25];
    const float* offset  = (const float*)d_in[26];
    const float* offsetc = (const float*)d_in[27];

    dim3 g2(72, 1, 2);
    k_rdown<<<g2, 128>>>(x, x_c, w_down, b_down, w_downc, b_downc);

    dim3 g3(72, 1, 2);
    k_proj<<<g3, 128>>>(w_q, b_q, w_k, b_k, w_v, b_v,
                        w_qsa, b_qsa, w_ksa, b_ksa, w_vsa, b_vsa,
                        offset, offsetc);

    dim3 g4(72, NB, 2);
    k_attn<<<g4, 128>>>();

    k_stats<<<128, 512>>>();

    dim3 g6(36, NB, 2);
    k_gnup<<<g6, 128>>>(gn_w, gn_b, gn_wsa, gn_bsa, w_up, b_up, w_upsa, b_upsa);

    k_final<<<18432, 256>>>(x_c, (float*)d_out);
}